// round 12
// baseline (speedup 1.0000x reference)
#include <cuda_runtime.h>
#include <cuda_fp16.h>
#include <math.h>
#include <stdint.h>

// ============================================================================
// MultiSizeProjHead via portable mma.sync — single-plane fp16 x fp16 (1 term)
// R12: 32x32 warp tiles, CTA tile 64(M)x128(N), 256 threads, 3 CTAs/SM
// (24 warps -> 6/SMSP) to fix latency-boundness found in R9-R11. KC=64,
// double-buffered cp.async. Weights pre-scaled x256; epilogues /256.
// ============================================================================
#define EMBED   1024
#define INTER   4096
#define SBASE   672
#define OUTD    21
#define NSAMP   256
#define PTOK    128
#define MROWS   (NSAMP * PTOK)
#define TTOT    2520        // 168 + 336 + 672 + 1344

#define KC       64                  // K per SMEM stage
#define TSTRIDE  144                 // bytes per smem row: 64 fp16 + 16 pad
#define TILE_A   (64 * TSTRIDE)      // 9216 B   (64 x 64 fp16 A tile)
#define TILE_BB  (128 * TSTRIDE)     // 18432 B  (128 x 64 fp16 B tile)
#define STAGE_B  (TILE_A + TILE_BB)  // 27648
#define SMEM_TOTAL (2 * STAGE_B)     // double buffered: 55296 B (3 CTAs/SM)

#define WSCALE   256.0f
#define INVWS    0.00390625f         // 1/256

__device__ __constant__ int c_T[4]    = {168, 336, 672, 1344};
__device__ __constant__ int c_Toff[4] = {0, 168, 504, 1176};

// ---------------- device scratch (no runtime allocation allowed) -----------
__device__ __half g_xf [(size_t)MROWS * EMBED];     // x, fp16
__device__ __half g_wi [(size_t)INTER * EMBED];     // W_in*256, fp16
__device__ __half g_xsf[(size_t)MROWS * INTER];     // xs, fp16
__device__ __half g_w2 [(size_t)TTOT * INTER];      // interp W_shared^T *256, t-major
__device__ __half g_wr [(size_t)TTOT * EMBED];      // interp W_res^T *256, t-major
__device__ float g_b2[TTOT];
__device__ float g_br[TTOT];

// ---------------- portable PTX helpers -------------------------------------
__device__ __forceinline__ uint32_t smem_to_u32(const void* p) {
    uint32_t a;
    asm("{ .reg .u64 t; cvta.to.shared.u64 t, %1; cvt.u32.u64 %0, t; }" : "=r"(a) : "l"(p));
    return a;
}
__device__ __forceinline__ void cp_async16(uint32_t dst, const void* src, uint32_t src_bytes) {
    asm volatile("cp.async.cg.shared.global [%0], [%1], 16, %2;"
                 :: "r"(dst), "l"(src), "r"(src_bytes) : "memory");
}
#define CP_COMMIT() asm volatile("cp.async.commit_group;" ::: "memory")
#define CP_WAIT0()  asm volatile("cp.async.wait_group 0;" ::: "memory")

__device__ __forceinline__ void ldsm_x4(uint32_t* r, uint32_t addr) {
    asm volatile("ldmatrix.sync.aligned.m8n8.x4.shared.b16 {%0,%1,%2,%3}, [%4];"
                 : "=r"(r[0]), "=r"(r[1]), "=r"(r[2]), "=r"(r[3]) : "r"(addr));
}
__device__ __forceinline__ void mma16816(float* c, const uint32_t* a, uint32_t b0, uint32_t b1) {
    asm volatile("mma.sync.aligned.m16n8k16.row.col.f32.f16.f16.f32 "
                 "{%0,%1,%2,%3}, {%4,%5,%6,%7}, {%8,%9}, {%0,%1,%2,%3};"
                 : "+f"(c[0]), "+f"(c[1]), "+f"(c[2]), "+f"(c[3])
                 : "r"(a[0]), "r"(a[1]), "r"(a[2]), "r"(a[3]), "r"(b0), "r"(b1));
}
__device__ __forceinline__ uint32_t pack2h(__half a, __half b) {
    return (uint32_t)__half_as_ushort(a) | ((uint32_t)__half_as_ushort(b) << 16);
}

// async-load one ROWSx64 fp16 tile (rows padded to 144B); rows >= vrows zero-fill
template<int ROWS>
__device__ __forceinline__ void load_tile_async(uint32_t sdst, const __half* __restrict__ src,
                                                long row0, long stride, int k0, int tid, int vrows) {
#pragma unroll
    for (int i = 0; i < ROWS / 32; i++) {      // 256 threads, 8 chunks/row
        const int c = tid + (i << 8);
        const int row = c >> 3, c8 = c & 7;
        const uint32_t d = sdst + (uint32_t)(row * TSTRIDE + c8 * 16);
        const bool ok = (row < vrows);
        const long srow = ok ? (row0 + row) : row0;
        const void* s = src + srow * stride + k0 + c8 * 8;
        cp_async16(d, s, ok ? 16u : 0u);
    }
}

// one KC=64 stage of 1-term MMA: acc += A*B   (warp tile 32x32)
__device__ __forceinline__ void mma_stage(uint32_t base, int lane, int warp_m, int warp_n,
                                          float acc[2][4][4]) {
    const int lr = lane & 7, lg = lane >> 3;
    const int rowSel = ((lg & 1) << 3) + lr;
    const int colHalf = (lg >> 1) << 3;
#pragma unroll
    for (int k16 = 0; k16 < KC; k16 += 16) {
        const uint32_t colOff = (uint32_t)((k16 + colHalf) * 2);
        uint32_t a[2][4], b[2][4];
#pragma unroll
        for (int i = 0; i < 2; i++) {
            const uint32_t addr = base + (uint32_t)((warp_m * 32 + i * 16 + rowSel) * TSTRIDE) + colOff;
            ldsm_x4(a[i], addr);
        }
#pragma unroll
        for (int jj = 0; jj < 2; jj++) {
            const uint32_t addr = base + TILE_A +
                (uint32_t)((warp_n * 32 + jj * 16 + rowSel) * TSTRIDE) + colOff;
            ldsm_x4(b[jj], addr);
        }
#pragma unroll
        for (int i = 0; i < 2; i++)
#pragma unroll
            for (int j = 0; j < 4; j++)
                mma16816(acc[i][j], a[i], b[j >> 1][j & 1], b[j >> 1][(j & 1) + 2]);
    }
}

// ---------------- prep kernel 1: x -> fp16, W_in -> fp16 (x256) ------------
__global__ void split_inputs_kernel(const float* __restrict__ x, const float* __restrict__ W_in) {
    const long nx = (long)MROWS * EMBED;
    const long nw = (long)INTER * EMBED;
    const long i = blockIdx.x * (long)blockDim.x + threadIdx.x;
    if (i >= nx + nw) return;
    if (i < nx) {
        g_xf[i] = __float2half_rn(x[i]);
    } else {
        const long j = i - nx;
        g_wi[j] = __float2half_rn(W_in[j] * WSCALE);
    }
}

// ---------------- prep kernel 2: interpolated head weights (t-major) -------
__device__ __forceinline__ void interp_coef(int tg, int& i0, int& i1, float& lam) {
    const int s = (tg < 168) ? 0 : (tg < 504) ? 1 : (tg < 1176) ? 2 : 3;
    const int t = tg - c_Toff[s];
    const float scale = (float)SBASE / (float)c_T[s];
    float src = fmaxf(((float)t + 0.5f) * scale - 0.5f, 0.0f);
    i0 = (int)src;                  // src >= 0 -> trunc == floor
    if (i0 > SBASE - 1) i0 = SBASE - 1;
    i1 = min(i0 + 1, SBASE - 1);
    lam = src - (float)i0;
}

__global__ void build_weights_kernel(const float* __restrict__ Ws, const float* __restrict__ bs,
                                     const float* __restrict__ Wr, const float* __restrict__ brs) {
    const long n2 = (long)TTOT * INTER;
    const long nr = (long)TTOT * EMBED;
    const long total = n2 + nr + 2 * TTOT;
    const long i = blockIdx.x * (long)blockDim.x + threadIdx.x;
    if (i >= total) return;
    int i0, i1; float lam;
    if (i < n2) {
        const int t = (int)(i / INTER), k = (int)(i % INTER);
        interp_coef(t, i0, i1, lam);
        const float v = Ws[(long)i0 * INTER + k] * (1.0f - lam) + Ws[(long)i1 * INTER + k] * lam;
        g_w2[i] = __float2half_rn(v * WSCALE);
    } else if (i < n2 + nr) {
        const long j = i - n2;
        const int t = (int)(j / EMBED), k = (int)(j % EMBED);
        interp_coef(t, i0, i1, lam);
        const float v = Wr[(long)i0 * EMBED + k] * (1.0f - lam) + Wr[(long)i1 * EMBED + k] * lam;
        g_wr[j] = __float2half_rn(v * WSCALE);
    } else if (i < n2 + nr + TTOT) {
        const int t = (int)(i - n2 - nr);
        interp_coef(t, i0, i1, lam);
        g_b2[t] = bs[i0] * (1.0f - lam) + bs[i1] * lam;
    } else {
        const int t = (int)(i - n2 - nr - TTOT);
        interp_coef(t, i0, i1, lam);
        g_br[t] = brs[i0] * (1.0f - lam) + brs[i1] * lam;
    }
}

// ---------------- GEMM1: xs = x @ W_in^T + b_in ------------------------------
// CTA tile 64(M) x 128(N), 8 warps of 32x32 (2x4 grid).
__global__ void __launch_bounds__(256, 3)
gemm1_kernel(const float* __restrict__ b_in) {
    extern __shared__ char smem[];
    const uint32_t sb = smem_to_u32(smem);
    const int tid = threadIdx.x;
    const int lane = tid & 31, wid = tid >> 5;
    const int warp_m = wid & 1, warp_n = wid >> 1;     // 2 x 4
    const long bm = (long)blockIdx.y * 64;
    const long bn = (long)blockIdx.x * 128;

    float acc[2][4][4];
#pragma unroll
    for (int i = 0; i < 2; i++)
#pragma unroll
        for (int j = 0; j < 4; j++)
#pragma unroll
            for (int e = 0; e < 4; e++) acc[i][j][e] = 0.0f;

    {
        load_tile_async<64> (sb,          g_xf, bm, EMBED, 0, tid, 64);
        load_tile_async<128>(sb + TILE_A, g_wi, bn, EMBED, 0, tid, 128);
        CP_COMMIT();
    }
    const int nK = EMBED / KC;
    for (int ks = 0; ks < nK; ks++) {
        CP_WAIT0();
        __syncthreads();
        if (ks + 1 < nK) {
            const uint32_t base = sb + ((ks + 1) & 1) * STAGE_B;
            const int k0 = (ks + 1) * KC;
            load_tile_async<64> (base,          g_xf, bm, EMBED, k0, tid, 64);
            load_tile_async<128>(base + TILE_A, g_wi, bn, EMBED, k0, tid, 128);
            CP_COMMIT();
        }
        mma_stage(sb + (ks & 1) * STAGE_B, lane, warp_m, warp_n, acc);
    }

    // epilogue: acc/256 + b_in -> fp16 single plane
    const int r0 = lane >> 2;
    const int c0 = (lane & 3) * 2;
#pragma unroll
    for (int i = 0; i < 2; i++) {
        const long rowA = bm + warp_m * 32 + i * 16 + r0;
        const long rowB = rowA + 8;
#pragma unroll
        for (int j = 0; j < 4; j++) {
            const long col = bn + warp_n * 32 + j * 8 + c0;
            const float bi0 = b_in[col], bi1 = b_in[col + 1];
            *(uint32_t*)(g_xsf + rowA * INTER + col) =
                pack2h(__float2half_rn(acc[i][j][0] * INVWS + bi0),
                       __float2half_rn(acc[i][j][1] * INVWS + bi1));
            *(uint32_t*)(g_xsf + rowB * INTER + col) =
                pack2h(__float2half_rn(acc[i][j][2] * INVWS + bi0),
                       __float2half_rn(acc[i][j][3] * INVWS + bi1));
        }
    }
}

// ---------------- head kernel: silu(xs@w2+b2) + x@wr+br + padding ----------
// blockIdx.y = sample*2 + mhalf (64-row half of the sample's 128 tokens).
// Single accumulator bank: silu output rescaled x256 so pass-2 (weights x256)
// accumulates in place; store multiplies by 1/256.
__global__ void __launch_bounds__(256, 3)
head_kernel(const int* __restrict__ psz, float* __restrict__ out, int max_dim) {
    const int n     = blockIdx.y >> 1;
    const int mhalf = blockIdx.y & 1;
    const int t0 = blockIdx.x * 128;
    const int tid = threadIdx.x;

    const int ps = psz[n];
    const int T = ps * OUTD;
    const int s4 = (ps == 8) ? 0 : (ps == 16) ? 1 : (ps == 32) ? 2 : 3;
    const int toff = c_Toff[s4];
    float* outBase = out + ((size_t)n * PTOK + mhalf * 64) * max_dim;

    if (t0 >= T) {  // pure zero-pad tile (64 rows of this half)
        const int colq = min(128, max_dim - t0) >> 2;
        const float4 z = make_float4(0.f, 0.f, 0.f, 0.f);
        for (int idx = tid; idx < 64 * colq; idx += 256) {
            const int r = idx / colq, c = idx % colq;
            *reinterpret_cast<float4*>(outBase + (size_t)r * max_dim + t0 + c * 4) = z;
        }
        return;
    }

    extern __shared__ char smem[];
    const uint32_t sb = smem_to_u32(smem);
    const int lane = tid & 31, wid = tid >> 5;
    const int warp_m = wid & 1, warp_n = wid >> 1;

    const int tmax = min(T - t0, 128);
    const long arow = (long)n * PTOK + mhalf * 64;
    const long brow = (long)toff + t0;

    float acc[2][4][4];
#pragma unroll
    for (int i = 0; i < 2; i++)
#pragma unroll
        for (int j = 0; j < 4; j++)
#pragma unroll
            for (int e = 0; e < 4; e++) acc[i][j][e] = 0.0f;

    const int r0 = lane >> 2;
    const int c0 = (lane & 3) * 2;

    // ---- pass 1: lin = xs @ w2_seg^T  (K = 4096) ----
    {
        load_tile_async<64> (sb,          g_xsf, arow, INTER, 0, tid, 64);
        load_tile_async<128>(sb + TILE_A, g_w2,  brow, INTER, 0, tid, tmax);
        CP_COMMIT();
    }
    const int nK1 = INTER / KC;
    for (int ks = 0; ks < nK1; ks++) {
        CP_WAIT0();
        __syncthreads();
        if (ks + 1 < nK1) {
            const uint32_t base = sb + ((ks + 1) & 1) * STAGE_B;
            const int k0 = (ks + 1) * KC;
            load_tile_async<64> (base,          g_xsf, arow, INTER, k0, tid, 64);
            load_tile_async<128>(base + TILE_A, g_w2,  brow, INTER, k0, tid, tmax);
            CP_COMMIT();
        }
        mma_stage(sb + (ks & 1) * STAGE_B, lane, warp_m, warp_n, acc);
    }

    // ---- silu(acc/256 + b2), rescaled x256 so pass 2 accumulates in place --
#pragma unroll
    for (int j = 0; j < 4; j++) {
        const int col = t0 + warp_n * 32 + j * 8 + c0;
        const float b20 = (col     < T) ? g_b2[toff + col]     : 0.0f;
        const float b21 = (col + 1 < T) ? g_b2[toff + col + 1] : 0.0f;
#pragma unroll
        for (int i = 0; i < 2; i++) {
            float v;
            v = acc[i][j][0] * INVWS + b20; acc[i][j][0] = v / (1.0f + __expf(-v)) * WSCALE;
            v = acc[i][j][1] * INVWS + b21; acc[i][j][1] = v / (1.0f + __expf(-v)) * WSCALE;
            v = acc[i][j][2] * INVWS + b20; acc[i][j][2] = v / (1.0f + __expf(-v)) * WSCALE;
            v = acc[i][j][3] * INVWS + b21; acc[i][j][3] = v / (1.0f + __expf(-v)) * WSCALE;
        }
    }

    // ---- pass 2: acc += x @ (wr*256)_seg^T  (K = 1024), same registers ----
    {
        load_tile_async<64> (sb,          g_xf, arow, EMBED, 0, tid, 64);
        load_tile_async<128>(sb + TILE_A, g_wr, brow, EMBED, 0, tid, tmax);
        CP_COMMIT();
    }
    const int nK2 = EMBED / KC;
    for (int ks = 0; ks < nK2; ks++) {
        CP_WAIT0();
        __syncthreads();
        if (ks + 1 < nK2) {
            const uint32_t base = sb + ((ks + 1) & 1) * STAGE_B;
            const int k0 = (ks + 1) * KC;
            load_tile_async<64> (base,          g_xf, arow, EMBED, k0, tid, 64);
            load_tile_async<128>(base + TILE_A, g_wr, brow, EMBED, k0, tid, tmax);
            CP_COMMIT();
        }
        mma_stage(sb + (ks & 1) * STAGE_B, lane, warp_m, warp_n, acc);
    }

    // ---- store: acc/256 + br (cols < T), zeros to max_dim ----
#pragma unroll
    for (int i = 0; i < 2; i++) {
        const int rowA = warp_m * 32 + i * 16 + r0;
#pragma unroll
        for (int j = 0; j < 4; j++) {
            const int col = t0 + warp_n * 32 + j * 8 + c0;
            if (col >= max_dim) continue;
            float2 v0, v1;
            if (col < T) {   // T even, col even -> col+1 < T too
                const float br0 = g_br[toff + col], br1 = g_br[toff + col + 1];
                v0 = make_float2(acc[i][j][0] * INVWS + br0, acc[i][j][1] * INVWS + br1);
                v1 = make_float2(acc[i][j][2] * INVWS + br0, acc[i][j][3] * INVWS + br1);
            } else {
                v0 = make_float2(0.f, 0.f);
                v1 = v0;
            }
            *reinterpret_cast<float2*>(outBase + (size_t)rowA * max_dim + col) = v0;
            *reinterpret_cast<float2*>(outBase + (size_t)(rowA + 8) * max_dim + col) = v1;
        }
    }
}

// ----------------------------------------------------------------------------
extern "C" void kernel_launch(void* const* d_in, const int* in_sizes, int n_in,
                              void* d_out, int out_size)
{
    const float* x     = (const float*)d_in[0];
    const int*   psz   = (const int*)d_in[1];
    const float* W_in  = (const float*)d_in[2];
    const float* b_in  = (const float*)d_in[3];
    const float* W_sh  = (const float*)d_in[4];
    const float* b_sh  = (const float*)d_in[5];
    const float* W_res = (const float*)d_in[6];
    const float* b_res = (const float*)d_in[7];
    float* out = (float*)d_out;

    const int max_dim = out_size / (NSAMP * PTOK);

    cudaFuncSetAttribute(gemm1_kernel, cudaFuncAttributeMaxDynamicSharedMemorySize, SMEM_TOTAL);
    cudaFuncSetAttribute(head_kernel,  cudaFuncAttributeMaxDynamicSharedMemorySize, SMEM_TOTAL);

    // 1) x -> fp16; W_in -> fp16 (x256)
    {
        const long total = (long)MROWS * EMBED + (long)INTER * EMBED;
        split_inputs_kernel<<<(unsigned)((total + 255) / 256), 256>>>(x, W_in);
    }
    // 2) interpolated head weights (fp16, x256, t-major) + fp32 biases
    {
        const long total = (long)TTOT * INTER + (long)TTOT * EMBED + 2L * TTOT;
        build_weights_kernel<<<(unsigned)((total + 255) / 256), 256>>>(W_sh, b_sh, W_res, b_res);
    }
    // 3) xs = x @ W_in^T + b_in
    {
        dim3 g(INTER / 128, MROWS / 64);    // (32, 512)
        gemm1_kernel<<<g, 256, SMEM_TOTAL>>>(b_in);
    }
    // 4) fused per-sample heads + zero padding (two 64-row halves per sample)
    {
        dim3 g((max_dim + 127) / 128, NSAMP * 2);
        head_kernel<<<g, 256, SMEM_TOTAL>>>(psz, out, max_dim);
    }
}

// round 13
// speedup vs baseline: 1.3637x; 1.3637x over previous
#include <cuda_runtime.h>
#include <cuda_fp16.h>
#include <math.h>
#include <stdint.h>

// ============================================================================
// MultiSizeProjHead via portable mma.sync — single-plane fp16 x fp16 (1 term)
// R13 = R9 (proven best: 64x32 warp tiles, 256 thr, 2 CTAs/SM, KC=64, double
// buffer) + tail-warp skip in partial t-tiles + merged prep kernel.
// Weights pre-scaled x256 (exact); epilogues multiply by 1/256.
// ============================================================================
#define EMBED   1024
#define INTER   4096
#define SBASE   672
#define OUTD    21
#define NSAMP   256
#define PTOK    128
#define MROWS   (NSAMP * PTOK)
#define TTOT    2520        // 168 + 336 + 672 + 1344

#define KC       64                  // K per SMEM stage
#define TSTRIDE  144                 // bytes per smem row: 64 fp16 + 16 pad
#define TILE_B   (128 * TSTRIDE)     // 18432 bytes per 128x64 tile
#define STAGE_B  (2 * TILE_B)        // A, B = 36864
#define SMEM_TOTAL (2 * STAGE_B)     // double buffered: 73728 B

#define WSCALE   256.0f
#define INVWS    0.00390625f         // 1/256

__device__ __constant__ int c_T[4]    = {168, 336, 672, 1344};
__device__ __constant__ int c_Toff[4] = {0, 168, 504, 1176};

// ---------------- device scratch (no runtime allocation allowed) -----------
__device__ __half g_xf [(size_t)MROWS * EMBED];     // x, fp16
__device__ __half g_wi [(size_t)INTER * EMBED];     // W_in*256, fp16
__device__ __half g_xsf[(size_t)MROWS * INTER];     // xs, fp16
__device__ __half g_w2 [(size_t)TTOT * INTER];      // interp W_shared^T *256, t-major
__device__ __half g_wr [(size_t)TTOT * EMBED];      // interp W_res^T *256, t-major
__device__ float g_b2[TTOT];
__device__ float g_br[TTOT];

// ---------------- portable PTX helpers -------------------------------------
__device__ __forceinline__ uint32_t smem_to_u32(const void* p) {
    uint32_t a;
    asm("{ .reg .u64 t; cvta.to.shared.u64 t, %1; cvt.u32.u64 %0, t; }" : "=r"(a) : "l"(p));
    return a;
}
__device__ __forceinline__ void cp_async16(uint32_t dst, const void* src, uint32_t src_bytes) {
    asm volatile("cp.async.cg.shared.global [%0], [%1], 16, %2;"
                 :: "r"(dst), "l"(src), "r"(src_bytes) : "memory");
}
#define CP_COMMIT() asm volatile("cp.async.commit_group;" ::: "memory")
#define CP_WAIT0()  asm volatile("cp.async.wait_group 0;" ::: "memory")

__device__ __forceinline__ void ldsm_x4(uint32_t* r, uint32_t addr) {
    asm volatile("ldmatrix.sync.aligned.m8n8.x4.shared.b16 {%0,%1,%2,%3}, [%4];"
                 : "=r"(r[0]), "=r"(r[1]), "=r"(r[2]), "=r"(r[3]) : "r"(addr));
}
__device__ __forceinline__ void mma16816(float* c, const uint32_t* a, uint32_t b0, uint32_t b1) {
    asm volatile("mma.sync.aligned.m16n8k16.row.col.f32.f16.f16.f32 "
                 "{%0,%1,%2,%3}, {%4,%5,%6,%7}, {%8,%9}, {%0,%1,%2,%3};"
                 : "+f"(c[0]), "+f"(c[1]), "+f"(c[2]), "+f"(c[3])
                 : "r"(a[0]), "r"(a[1]), "r"(a[2]), "r"(a[3]), "r"(b0), "r"(b1));
}
__device__ __forceinline__ uint32_t pack2h(__half a, __half b) {
    return (uint32_t)__half_as_ushort(a) | ((uint32_t)__half_as_ushort(b) << 16);
}

// async-load one 128x64 fp16 tile (rows padded to 144B); rows >= vrows zero-fill
__device__ __forceinline__ void load_tile_async(uint32_t sdst, const __half* __restrict__ src,
                                                long row0, long stride, int k0, int tid, int vrows) {
#pragma unroll
    for (int i = 0; i < 4; i++) {
        const int c = tid + (i << 8);          // 0..1023 chunks of 16B
        const int row = c >> 3, c8 = c & 7;
        const uint32_t d = sdst + (uint32_t)(row * TSTRIDE + c8 * 16);
        const bool ok = (row < vrows);
        const long srow = ok ? (row0 + row) : row0;
        const void* s = src + srow * stride + k0 + c8 * 8;
        cp_async16(d, s, ok ? 16u : 0u);
    }
}

// one KC=64 stage of 1-term MMA: acc += A*B   (warp tile 64x32)
__device__ __forceinline__ void mma_stage(uint32_t base, int lane, int warp_m, int warp_n,
                                          float acc[4][4][4]) {
    const int lr = lane & 7, lg = lane >> 3;
    const int rowSel = ((lg & 1) << 3) + lr;
    const int colHalf = (lg >> 1) << 3;
#pragma unroll
    for (int k16 = 0; k16 < KC; k16 += 16) {
        const uint32_t colOff = (uint32_t)((k16 + colHalf) * 2);
        uint32_t a[4][4], b[2][4];
#pragma unroll
        for (int i = 0; i < 4; i++) {
            const uint32_t addr = base + (uint32_t)((warp_m * 64 + i * 16 + rowSel) * TSTRIDE) + colOff;
            ldsm_x4(a[i], addr);
        }
#pragma unroll
        for (int jj = 0; jj < 2; jj++) {
            const uint32_t addr = base + TILE_B +
                (uint32_t)((warp_n * 32 + jj * 16 + rowSel) * TSTRIDE) + colOff;
            ldsm_x4(b[jj], addr);
        }
#pragma unroll
        for (int i = 0; i < 4; i++)
#pragma unroll
            for (int j = 0; j < 4; j++)
                mma16816(acc[i][j], a[i], b[j >> 1][j & 1], b[j >> 1][(j & 1) + 2]);
    }
}

// ---------------- merged prep: x/W_in -> fp16 (x256 for W), interp weights --
__device__ __forceinline__ void interp_coef(int tg, int& i0, int& i1, float& lam) {
    const int s = (tg < 168) ? 0 : (tg < 504) ? 1 : (tg < 1176) ? 2 : 3;
    const int t = tg - c_Toff[s];
    const float scale = (float)SBASE / (float)c_T[s];
    float src = fmaxf(((float)t + 0.5f) * scale - 0.5f, 0.0f);
    i0 = (int)src;                  // src >= 0 -> trunc == floor
    if (i0 > SBASE - 1) i0 = SBASE - 1;
    i1 = min(i0 + 1, SBASE - 1);
    lam = src - (float)i0;
}

__global__ void prep_kernel(const float* __restrict__ x, const float* __restrict__ W_in,
                            const float* __restrict__ Ws, const float* __restrict__ bs,
                            const float* __restrict__ Wr, const float* __restrict__ brs) {
    const long nx = (long)MROWS * EMBED;
    const long nw = (long)INTER * EMBED;
    const long n2 = (long)TTOT * INTER;
    const long nr = (long)TTOT * EMBED;
    const long total = nx + nw + n2 + nr + 2 * TTOT;
    const long i = blockIdx.x * (long)blockDim.x + threadIdx.x;
    if (i >= total) return;
    if (i < nx) {
        g_xf[i] = __float2half_rn(x[i]);
    } else if (i < nx + nw) {
        const long j = i - nx;
        g_wi[j] = __float2half_rn(W_in[j] * WSCALE);
    } else if (i < nx + nw + n2) {
        const long j = i - nx - nw;
        const int t = (int)(j / INTER), k = (int)(j % INTER);
        int i0, i1; float lam;
        interp_coef(t, i0, i1, lam);
        const float v = Ws[(long)i0 * INTER + k] * (1.0f - lam) + Ws[(long)i1 * INTER + k] * lam;
        g_w2[j] = __float2half_rn(v * WSCALE);
    } else if (i < nx + nw + n2 + nr) {
        const long j = i - nx - nw - n2;
        const int t = (int)(j / EMBED), k = (int)(j % EMBED);
        int i0, i1; float lam;
        interp_coef(t, i0, i1, lam);
        const float v = Wr[(long)i0 * EMBED + k] * (1.0f - lam) + Wr[(long)i1 * EMBED + k] * lam;
        g_wr[j] = __float2half_rn(v * WSCALE);
    } else if (i < nx + nw + n2 + nr + TTOT) {
        const int t = (int)(i - nx - nw - n2 - nr);
        int i0, i1; float lam;
        interp_coef(t, i0, i1, lam);
        g_b2[t] = bs[i0] * (1.0f - lam) + bs[i1] * lam;
    } else {
        const int t = (int)(i - nx - nw - n2 - nr - TTOT);
        int i0, i1; float lam;
        interp_coef(t, i0, i1, lam);
        g_br[t] = brs[i0] * (1.0f - lam) + brs[i1] * lam;
    }
}

// ---------------- GEMM1: xs = x @ W_in^T + b_in ------------------------------
__global__ void __launch_bounds__(256, 2)
gemm1_kernel(const float* __restrict__ b_in) {
    extern __shared__ char smem[];
    const uint32_t sb = smem_to_u32(smem);
    const int tid = threadIdx.x;
    const int lane = tid & 31, wid = tid >> 5;
    const int warp_m = wid >> 2, warp_n = wid & 3;
    const long bm = (long)blockIdx.y * 128;
    const long bn = (long)blockIdx.x * 128;

    float acc[4][4][4];
#pragma unroll
    for (int i = 0; i < 4; i++)
#pragma unroll
        for (int j = 0; j < 4; j++)
#pragma unroll
            for (int e = 0; e < 4; e++) acc[i][j][e] = 0.0f;

    {
        load_tile_async(sb,          g_xf, bm, EMBED, 0, tid, 128);
        load_tile_async(sb + TILE_B, g_wi, bn, EMBED, 0, tid, 128);
        CP_COMMIT();
    }
    const int nK = EMBED / KC;
    for (int ks = 0; ks < nK; ks++) {
        CP_WAIT0();
        __syncthreads();
        if (ks + 1 < nK) {
            const uint32_t base = sb + ((ks + 1) & 1) * STAGE_B;
            const int k0 = (ks + 1) * KC;
            load_tile_async(base,          g_xf, bm, EMBED, k0, tid, 128);
            load_tile_async(base + TILE_B, g_wi, bn, EMBED, k0, tid, 128);
            CP_COMMIT();
        }
        mma_stage(sb + (ks & 1) * STAGE_B, lane, warp_m, warp_n, acc);
    }

    // epilogue: acc/256 + b_in -> fp16 single plane
    const int r0 = lane >> 2;
    const int c0 = (lane & 3) * 2;
#pragma unroll
    for (int i = 0; i < 4; i++) {
        const long rowA = bm + warp_m * 64 + i * 16 + r0;
        const long rowB = rowA + 8;
#pragma unroll
        for (int j = 0; j < 4; j++) {
            const long col = bn + warp_n * 32 + j * 8 + c0;
            const float bi0 = b_in[col], bi1 = b_in[col + 1];
            *(uint32_t*)(g_xsf + rowA * INTER + col) =
                pack2h(__float2half_rn(acc[i][j][0] * INVWS + bi0),
                       __float2half_rn(acc[i][j][1] * INVWS + bi1));
            *(uint32_t*)(g_xsf + rowB * INTER + col) =
                pack2h(__float2half_rn(acc[i][j][2] * INVWS + bi0),
                       __float2half_rn(acc[i][j][3] * INVWS + bi1));
        }
    }
}

// ---------------- head kernel: silu(xs@w2+b2) + x@wr+br + padding ----------
// Single accumulator bank: silu output rescaled x256 so pass-2 (weights x256)
// accumulates in place; store multiplies by 1/256.
// Tail-warp skip: warps whose 32-col slice lies fully past tmax (zero-filled B)
// skip LDSM+MMA entirely — their acc stays 0 and is never stored (col >= T).
__global__ void __launch_bounds__(256, 2)
head_kernel(const int* __restrict__ psz, float* __restrict__ out, int max_dim) {
    const int n  = blockIdx.y;
    const int t0 = blockIdx.x * 128;
    const int tid = threadIdx.x;

    const int ps = psz[n];
    const int T = ps * OUTD;
    const int s4 = (ps == 8) ? 0 : (ps == 16) ? 1 : (ps == 32) ? 2 : 3;
    const int toff = c_Toff[s4];
    float* outBase = out + (size_t)n * PTOK * max_dim;

    if (t0 >= T) {  // pure zero-pad tile
        const int colq = min(128, max_dim - t0) >> 2;
        const float4 z = make_float4(0.f, 0.f, 0.f, 0.f);
        for (int idx = tid; idx < PTOK * colq; idx += 256) {
            const int r = idx / colq, c = idx % colq;
            *reinterpret_cast<float4*>(outBase + (size_t)r * max_dim + t0 + c * 4) = z;
        }
        return;
    }

    extern __shared__ char smem[];
    const uint32_t sb = smem_to_u32(smem);
    const int lane = tid & 31, wid = tid >> 5;
    const int warp_m = wid >> 2, warp_n = wid & 3;

    const int tmax = min(T - t0, 128);
    const bool active = (warp_n * 32 < tmax);   // any valid cols in this warp?
    const long arow = (long)n * PTOK;
    const long brow = (long)toff + t0;

    float acc[4][4][4];
#pragma unroll
    for (int i = 0; i < 4; i++)
#pragma unroll
        for (int j = 0; j < 4; j++)
#pragma unroll
            for (int e = 0; e < 4; e++) acc[i][j][e] = 0.0f;

    const int r0 = lane >> 2;
    const int c0 = (lane & 3) * 2;

    // ---- pass 1: lin = xs @ w2_seg^T  (K = 4096) ----
    {
        load_tile_async(sb,          g_xsf, arow, INTER, 0, tid, 128);
        load_tile_async(sb + TILE_B, g_w2,  brow, INTER, 0, tid, tmax);
        CP_COMMIT();
    }
    const int nK1 = INTER / KC;
    for (int ks = 0; ks < nK1; ks++) {
        CP_WAIT0();
        __syncthreads();
        if (ks + 1 < nK1) {
            const uint32_t base = sb + ((ks + 1) & 1) * STAGE_B;
            const int k0 = (ks + 1) * KC;
            load_tile_async(base,          g_xsf, arow, INTER, k0, tid, 128);
            load_tile_async(base + TILE_B, g_w2,  brow, INTER, k0, tid, tmax);
            CP_COMMIT();
        }
        if (active)
            mma_stage(sb + (ks & 1) * STAGE_B, lane, warp_m, warp_n, acc);
    }

    // ---- silu(acc/256 + b2), rescaled x256 so pass 2 accumulates in place --
    if (active) {
#pragma unroll
        for (int j = 0; j < 4; j++) {
            const int col = t0 + warp_n * 32 + j * 8 + c0;
            const float b20 = (col     < T) ? g_b2[toff + col]     : 0.0f;
            const float b21 = (col + 1 < T) ? g_b2[toff + col + 1] : 0.0f;
#pragma unroll
            for (int i = 0; i < 4; i++) {
                float v;
                v = acc[i][j][0] * INVWS + b20; acc[i][j][0] = v / (1.0f + __expf(-v)) * WSCALE;
                v = acc[i][j][1] * INVWS + b21; acc[i][j][1] = v / (1.0f + __expf(-v)) * WSCALE;
                v = acc[i][j][2] * INVWS + b20; acc[i][j][2] = v / (1.0f + __expf(-v)) * WSCALE;
                v = acc[i][j][3] * INVWS + b21; acc[i][j][3] = v / (1.0f + __expf(-v)) * WSCALE;
            }
        }
    }

    // ---- pass 2: acc += x @ (wr*256)_seg^T  (K = 1024), same registers ----
    {
        load_tile_async(sb,          g_xf, arow, EMBED, 0, tid, 128);
        load_tile_async(sb + TILE_B, g_wr, brow, EMBED, 0, tid, tmax);
        CP_COMMIT();
    }
    const int nK2 = EMBED / KC;
    for (int ks = 0; ks < nK2; ks++) {
        CP_WAIT0();
        __syncthreads();
        if (ks + 1 < nK2) {
            const uint32_t base = sb + ((ks + 1) & 1) * STAGE_B;
            const int k0 = (ks + 1) * KC;
            load_tile_async(base,          g_xf, arow, EMBED, k0, tid, 128);
            load_tile_async(base + TILE_B, g_wr, brow, EMBED, k0, tid, tmax);
            CP_COMMIT();
        }
        if (active)
            mma_stage(sb + (ks & 1) * STAGE_B, lane, warp_m, warp_n, acc);
    }

    // ---- store: acc/256 + br (cols < T), zeros to max_dim ----
#pragma unroll
    for (int i = 0; i < 4; i++) {
        const int rowA = warp_m * 64 + i * 16 + r0;
#pragma unroll
        for (int j = 0; j < 4; j++) {
            const int col = t0 + warp_n * 32 + j * 8 + c0;
            if (col >= max_dim) continue;
            float2 v0, v1;
            if (col < T) {   // T even, col even -> col+1 < T too
                const float br0 = g_br[toff + col], br1 = g_br[toff + col + 1];
                v0 = make_float2(acc[i][j][0] * INVWS + br0, acc[i][j][1] * INVWS + br1);
                v1 = make_float2(acc[i][j][2] * INVWS + br0, acc[i][j][3] * INVWS + br1);
            } else {
                v0 = make_float2(0.f, 0.f);
                v1 = v0;
            }
            *reinterpret_cast<float2*>(outBase + (size_t)rowA * max_dim + col) = v0;
            *reinterpret_cast<float2*>(outBase + (size_t)(rowA + 8) * max_dim + col) = v1;
        }
    }
}

// ----------------------------------------------------------------------------
extern "C" void kernel_launch(void* const* d_in, const int* in_sizes, int n_in,
                              void* d_out, int out_size)
{
    const float* x     = (const float*)d_in[0];
    const int*   psz   = (const int*)d_in[1];
    const float* W_in  = (const float*)d_in[2];
    const float* b_in  = (const float*)d_in[3];
    const float* W_sh  = (const float*)d_in[4];
    const float* b_sh  = (const float*)d_in[5];
    const float* W_res = (const float*)d_in[6];
    const float* b_res = (const float*)d_in[7];
    float* out = (float*)d_out;

    const int max_dim = out_size / (NSAMP * PTOK);

    cudaFuncSetAttribute(gemm1_kernel, cudaFuncAttributeMaxDynamicSharedMemorySize, SMEM_TOTAL);
    cudaFuncSetAttribute(head_kernel,  cudaFuncAttributeMaxDynamicSharedMemorySize, SMEM_TOTAL);

    // 1) merged prep: x/W_in -> fp16 + interpolated head weights + biases
    {
        const long total = (long)MROWS * EMBED + (long)INTER * EMBED
                         + (long)TTOT * INTER + (long)TTOT * EMBED + 2L * TTOT;
        prep_kernel<<<(unsigned)((total + 255) / 256), 256>>>(x, W_in, W_sh, b_sh, W_res, b_res);
    }
    // 2) xs = x @ W_in^T + b_in
    {
        dim3 g(INTER / 128, MROWS / 128);   // (32, 256)
        gemm1_kernel<<<g, 256, SMEM_TOTAL>>>(b_in);
    }
    // 3) fused per-sample heads + zero padding
    {
        dim3 g((max_dim + 127) / 128, NSAMP);
        head_kernel<<<g, 256, SMEM_TOTAL>>>(psz, out, max_dim);
    }
}

// round 14
// speedup vs baseline: 1.4466x; 1.0607x over previous
#include <cuda_runtime.h>
#include <cuda_fp16.h>
#include <math.h>
#include <stdint.h>

// ============================================================================
// MultiSizeProjHead via portable mma.sync — single-plane fp16 x fp16 (1 term)
// R14 = R9 core (64x32 warp tiles, 256 thr, 2 CTAs/SM, KC=64, double buffer)
// + tail-warp skip + 8x-vectorized prep kernel (float4 loads, uint4 stores).
// Weights pre-scaled x256 (exact); epilogues multiply by 1/256.
// ============================================================================
#define EMBED   1024
#define INTER   4096
#define SBASE   672
#define OUTD    21
#define NSAMP   256
#define PTOK    128
#define MROWS   (NSAMP * PTOK)
#define TTOT    2520        // 168 + 336 + 672 + 1344

#define KC       64                  // K per SMEM stage
#define TSTRIDE  144                 // bytes per smem row: 64 fp16 + 16 pad
#define TILE_B   (128 * TSTRIDE)     // 18432 bytes per 128x64 tile
#define STAGE_B  (2 * TILE_B)        // A, B = 36864
#define SMEM_TOTAL (2 * STAGE_B)     // double buffered: 73728 B

#define WSCALE   256.0f
#define INVWS    0.00390625f         // 1/256

__device__ __constant__ int c_T[4]    = {168, 336, 672, 1344};
__device__ __constant__ int c_Toff[4] = {0, 168, 504, 1176};

// ---------------- device scratch (no runtime allocation allowed) -----------
__device__ __half g_xf [(size_t)MROWS * EMBED];     // x, fp16
__device__ __half g_wi [(size_t)INTER * EMBED];     // W_in*256, fp16
__device__ __half g_xsf[(size_t)MROWS * INTER];     // xs, fp16
__device__ __half g_w2 [(size_t)TTOT * INTER];      // interp W_shared^T *256, t-major
__device__ __half g_wr [(size_t)TTOT * EMBED];      // interp W_res^T *256, t-major
__device__ float g_b2[TTOT];
__device__ float g_br[TTOT];

// ---------------- portable PTX helpers -------------------------------------
__device__ __forceinline__ uint32_t smem_to_u32(const void* p) {
    uint32_t a;
    asm("{ .reg .u64 t; cvta.to.shared.u64 t, %1; cvt.u32.u64 %0, t; }" : "=r"(a) : "l"(p));
    return a;
}
__device__ __forceinline__ void cp_async16(uint32_t dst, const void* src, uint32_t src_bytes) {
    asm volatile("cp.async.cg.shared.global [%0], [%1], 16, %2;"
                 :: "r"(dst), "l"(src), "r"(src_bytes) : "memory");
}
#define CP_COMMIT() asm volatile("cp.async.commit_group;" ::: "memory")
#define CP_WAIT0()  asm volatile("cp.async.wait_group 0;" ::: "memory")

__device__ __forceinline__ void ldsm_x4(uint32_t* r, uint32_t addr) {
    asm volatile("ldmatrix.sync.aligned.m8n8.x4.shared.b16 {%0,%1,%2,%3}, [%4];"
                 : "=r"(r[0]), "=r"(r[1]), "=r"(r[2]), "=r"(r[3]) : "r"(addr));
}
__device__ __forceinline__ void mma16816(float* c, const uint32_t* a, uint32_t b0, uint32_t b1) {
    asm volatile("mma.sync.aligned.m16n8k16.row.col.f32.f16.f16.f32 "
                 "{%0,%1,%2,%3}, {%4,%5,%6,%7}, {%8,%9}, {%0,%1,%2,%3};"
                 : "+f"(c[0]), "+f"(c[1]), "+f"(c[2]), "+f"(c[3])
                 : "r"(a[0]), "r"(a[1]), "r"(a[2]), "r"(a[3]), "r"(b0), "r"(b1));
}
__device__ __forceinline__ uint32_t pack2h(__half a, __half b) {
    return (uint32_t)__half_as_ushort(a) | ((uint32_t)__half_as_ushort(b) << 16);
}
// pack 8 scaled floats (two float4) into 8 fp16
__device__ __forceinline__ uint4 cvt8(float4 a, float4 b, float s) {
    uint4 r;
    r.x = pack2h(__float2half_rn(a.x * s), __float2half_rn(a.y * s));
    r.y = pack2h(__float2half_rn(a.z * s), __float2half_rn(a.w * s));
    r.z = pack2h(__float2half_rn(b.x * s), __float2half_rn(b.y * s));
    r.w = pack2h(__float2half_rn(b.z * s), __float2half_rn(b.w * s));
    return r;
}

// async-load one 128x64 fp16 tile (rows padded to 144B); rows >= vrows zero-fill
__device__ __forceinline__ void load_tile_async(uint32_t sdst, const __half* __restrict__ src,
                                                long row0, long stride, int k0, int tid, int vrows) {
#pragma unroll
    for (int i = 0; i < 4; i++) {
        const int c = tid + (i << 8);          // 0..1023 chunks of 16B
        const int row = c >> 3, c8 = c & 7;
        const uint32_t d = sdst + (uint32_t)(row * TSTRIDE + c8 * 16);
        const bool ok = (row < vrows);
        const long srow = ok ? (row0 + row) : row0;
        const void* s = src + srow * stride + k0 + c8 * 8;
        cp_async16(d, s, ok ? 16u : 0u);
    }
}

// one KC=64 stage of 1-term MMA: acc += A*B   (warp tile 64x32)
__device__ __forceinline__ void mma_stage(uint32_t base, int lane, int warp_m, int warp_n,
                                          float acc[4][4][4]) {
    const int lr = lane & 7, lg = lane >> 3;
    const int rowSel = ((lg & 1) << 3) + lr;
    const int colHalf = (lg >> 1) << 3;
#pragma unroll
    for (int k16 = 0; k16 < KC; k16 += 16) {
        const uint32_t colOff = (uint32_t)((k16 + colHalf) * 2);
        uint32_t a[4][4], b[2][4];
#pragma unroll
        for (int i = 0; i < 4; i++) {
            const uint32_t addr = base + (uint32_t)((warp_m * 64 + i * 16 + rowSel) * TSTRIDE) + colOff;
            ldsm_x4(a[i], addr);
        }
#pragma unroll
        for (int jj = 0; jj < 2; jj++) {
            const uint32_t addr = base + TILE_B +
                (uint32_t)((warp_n * 32 + jj * 16 + rowSel) * TSTRIDE) + colOff;
            ldsm_x4(b[jj], addr);
        }
#pragma unroll
        for (int i = 0; i < 4; i++)
#pragma unroll
            for (int j = 0; j < 4; j++)
                mma16816(acc[i][j], a[i], b[j >> 1][j & 1], b[j >> 1][(j & 1) + 2]);
    }
}

// ---------------- vectorized prep: 8 contiguous elements per thread --------
__device__ __forceinline__ void interp_coef(int tg, int& i0, int& i1, float& lam) {
    const int s = (tg < 168) ? 0 : (tg < 504) ? 1 : (tg < 1176) ? 2 : 3;
    const int t = tg - c_Toff[s];
    const float scale = (float)SBASE / (float)c_T[s];
    float src = fmaxf(((float)t + 0.5f) * scale - 0.5f, 0.0f);
    i0 = (int)src;                  // src >= 0 -> trunc == floor
    if (i0 > SBASE - 1) i0 = SBASE - 1;
    i1 = min(i0 + 1, SBASE - 1);
    lam = src - (float)i0;
}
__device__ __forceinline__ float4 lerp4(float4 a, float4 b, float lam) {
    return make_float4(a.x + (b.x - a.x) * lam, a.y + (b.y - a.y) * lam,
                       a.z + (b.z - a.z) * lam, a.w + (b.w - a.w) * lam);
}
// NOTE on rounding: reference computes w0*(1-lam)+w1*lam; a+(b-a)*lam differs
// in ulps. Keep the exact reference form below instead.
__device__ __forceinline__ float4 mix4(float4 a, float4 b, float lam) {
    const float om = 1.0f - lam;
    return make_float4(a.x * om + b.x * lam, a.y * om + b.y * lam,
                       a.z * om + b.z * lam, a.w * om + b.w * lam);
}

__global__ void prep_kernel(const float* __restrict__ x, const float* __restrict__ W_in,
                            const float* __restrict__ Ws, const float* __restrict__ bs,
                            const float* __restrict__ Wr, const float* __restrict__ brs) {
    const long nx8 = (long)MROWS * EMBED / 8;
    const long nw8 = (long)INTER * EMBED / 8;
    const long n28 = (long)TTOT * INTER / 8;
    const long nr8 = (long)TTOT * EMBED / 8;
    const long nb8 = TTOT / 8;                 // 315
    const long total = nx8 + nw8 + n28 + nr8 + 2 * nb8;
    const long i = blockIdx.x * (long)blockDim.x + threadIdx.x;
    if (i >= total) return;

    if (i < nx8) {
        const long e = i * 8;
        const float4 a = *(const float4*)(x + e);
        const float4 b = *(const float4*)(x + e + 4);
        *(uint4*)(g_xf + e) = cvt8(a, b, 1.0f);
    } else if (i < nx8 + nw8) {
        const long e = (i - nx8) * 8;
        const float4 a = *(const float4*)(W_in + e);
        const float4 b = *(const float4*)(W_in + e + 4);
        *(uint4*)(g_wi + e) = cvt8(a, b, WSCALE);
    } else if (i < nx8 + nw8 + n28) {
        const long e = (i - nx8 - nw8) * 8;
        const int t = (int)(e / INTER), k = (int)(e % INTER);   // 8-chunk within one row
        int i0, i1; float lam;
        interp_coef(t, i0, i1, lam);
        const float4 a0 = *(const float4*)(Ws + (long)i0 * INTER + k);
        const float4 a1 = *(const float4*)(Ws + (long)i0 * INTER + k + 4);
        const float4 b0 = *(const float4*)(Ws + (long)i1 * INTER + k);
        const float4 b1 = *(const float4*)(Ws + (long)i1 * INTER + k + 4);
        *(uint4*)(g_w2 + e) = cvt8(mix4(a0, b0, lam), mix4(a1, b1, lam), WSCALE);
    } else if (i < nx8 + nw8 + n28 + nr8) {
        const long e = (i - nx8 - nw8 - n28) * 8;
        const int t = (int)(e / EMBED), k = (int)(e % EMBED);
        int i0, i1; float lam;
        interp_coef(t, i0, i1, lam);
        const float4 a0 = *(const float4*)(Wr + (long)i0 * EMBED + k);
        const float4 a1 = *(const float4*)(Wr + (long)i0 * EMBED + k + 4);
        const float4 b0 = *(const float4*)(Wr + (long)i1 * EMBED + k);
        const float4 b1 = *(const float4*)(Wr + (long)i1 * EMBED + k + 4);
        *(uint4*)(g_wr + e) = cvt8(mix4(a0, b0, lam), mix4(a1, b1, lam), WSCALE);
    } else if (i < nx8 + nw8 + n28 + nr8 + nb8) {
        const int t0 = (int)(i - nx8 - nw8 - n28 - nr8) * 8;
#pragma unroll
        for (int u = 0; u < 8; u++) {
            int i0, i1; float lam;
            interp_coef(t0 + u, i0, i1, lam);
            g_b2[t0 + u] = bs[i0] * (1.0f - lam) + bs[i1] * lam;
        }
    } else {
        const int t0 = (int)(i - nx8 - nw8 - n28 - nr8 - nb8) * 8;
#pragma unroll
        for (int u = 0; u < 8; u++) {
            int i0, i1; float lam;
            interp_coef(t0 + u, i0, i1, lam);
            g_br[t0 + u] = brs[i0] * (1.0f - lam) + brs[i1] * lam;
        }
    }
}

// ---------------- GEMM1: xs = x @ W_in^T + b_in ------------------------------
__global__ void __launch_bounds__(256, 2)
gemm1_kernel(const float* __restrict__ b_in) {
    extern __shared__ char smem[];
    const uint32_t sb = smem_to_u32(smem);
    const int tid = threadIdx.x;
    const int lane = tid & 31, wid = tid >> 5;
    const int warp_m = wid >> 2, warp_n = wid & 3;
    const long bm = (long)blockIdx.y * 128;
    const long bn = (long)blockIdx.x * 128;

    float acc[4][4][4];
#pragma unroll
    for (int i = 0; i < 4; i++)
#pragma unroll
        for (int j = 0; j < 4; j++)
#pragma unroll
            for (int e = 0; e < 4; e++) acc[i][j][e] = 0.0f;

    {
        load_tile_async(sb,          g_xf, bm, EMBED, 0, tid, 128);
        load_tile_async(sb + TILE_B, g_wi, bn, EMBED, 0, tid, 128);
        CP_COMMIT();
    }
    const int nK = EMBED / KC;
    for (int ks = 0; ks < nK; ks++) {
        CP_WAIT0();
        __syncthreads();
        if (ks + 1 < nK) {
            const uint32_t base = sb + ((ks + 1) & 1) * STAGE_B;
            const int k0 = (ks + 1) * KC;
            load_tile_async(base,          g_xf, bm, EMBED, k0, tid, 128);
            load_tile_async(base + TILE_B, g_wi, bn, EMBED, k0, tid, 128);
            CP_COMMIT();
        }
        mma_stage(sb + (ks & 1) * STAGE_B, lane, warp_m, warp_n, acc);
    }

    // epilogue: acc/256 + b_in -> fp16 single plane
    const int r0 = lane >> 2;
    const int c0 = (lane & 3) * 2;
#pragma unroll
    for (int i = 0; i < 4; i++) {
        const long rowA = bm + warp_m * 64 + i * 16 + r0;
        const long rowB = rowA + 8;
#pragma unroll
        for (int j = 0; j < 4; j++) {
            const long col = bn + warp_n * 32 + j * 8 + c0;
            const float bi0 = b_in[col], bi1 = b_in[col + 1];
            *(uint32_t*)(g_xsf + rowA * INTER + col) =
                pack2h(__float2half_rn(acc[i][j][0] * INVWS + bi0),
                       __float2half_rn(acc[i][j][1] * INVWS + bi1));
            *(uint32_t*)(g_xsf + rowB * INTER + col) =
                pack2h(__float2half_rn(acc[i][j][2] * INVWS + bi0),
                       __float2half_rn(acc[i][j][3] * INVWS + bi1));
        }
    }
}

// ---------------- head kernel: silu(xs@w2+b2) + x@wr+br + padding ----------
// Single accumulator bank: silu output rescaled x256 so pass-2 (weights x256)
// accumulates in place; store multiplies by 1/256. Tail warps (fully past
// tmax) skip LDSM+MMA; their acc is never stored.
__global__ void __launch_bounds__(256, 2)
head_kernel(const int* __restrict__ psz, float* __restrict__ out, int max_dim) {
    const int n  = blockIdx.y;
    const int t0 = blockIdx.x * 128;
    const int tid = threadIdx.x;

    const int ps = psz[n];
    const int T = ps * OUTD;
    const int s4 = (ps == 8) ? 0 : (ps == 16) ? 1 : (ps == 32) ? 2 : 3;
    const int toff = c_Toff[s4];
    float* outBase = out + (size_t)n * PTOK * max_dim;

    if (t0 >= T) {  // pure zero-pad tile
        const int colq = min(128, max_dim - t0) >> 2;
        const float4 z = make_float4(0.f, 0.f, 0.f, 0.f);
        for (int idx = tid; idx < PTOK * colq; idx += 256) {
            const int r = idx / colq, c = idx % colq;
            *reinterpret_cast<float4*>(outBase + (size_t)r * max_dim + t0 + c * 4) = z;
        }
        return;
    }

    extern __shared__ char smem[];
    const uint32_t sb = smem_to_u32(smem);
    const int lane = tid & 31, wid = tid >> 5;
    const int warp_m = wid >> 2, warp_n = wid & 3;

    const int tmax = min(T - t0, 128);
    const bool active = (warp_n * 32 < tmax);
    const long arow = (long)n * PTOK;
    const long brow = (long)toff + t0;

    float acc[4][4][4];
#pragma unroll
    for (int i = 0; i < 4; i++)
#pragma unroll
        for (int j = 0; j < 4; j++)
#pragma unroll
            for (int e = 0; e < 4; e++) acc[i][j][e] = 0.0f;

    const int r0 = lane >> 2;
    const int c0 = (lane & 3) * 2;

    // ---- pass 1: lin = xs @ w2_seg^T  (K = 4096) ----
    {
        load_tile_async(sb,          g_xsf, arow, INTER, 0, tid, 128);
        load_tile_async(sb + TILE_B, g_w2,  brow, INTER, 0, tid, tmax);
        CP_COMMIT();
    }
    const int nK1 = INTER / KC;
    for (int ks = 0; ks < nK1; ks++) {
        CP_WAIT0();
        __syncthreads();
        if (ks + 1 < nK1) {
            const uint32_t base = sb + ((ks + 1) & 1) * STAGE_B;
            const int k0 = (ks + 1) * KC;
            load_tile_async(base,          g_xsf, arow, INTER, k0, tid, 128);
            load_tile_async(base + TILE_B, g_w2,  brow, INTER, k0, tid, tmax);
            CP_COMMIT();
        }
        if (active)
            mma_stage(sb + (ks & 1) * STAGE_B, lane, warp_m, warp_n, acc);
    }

    // ---- silu(acc/256 + b2), rescaled x256 so pass 2 accumulates in place --
    if (active) {
#pragma unroll
        for (int j = 0; j < 4; j++) {
            const int col = t0 + warp_n * 32 + j * 8 + c0;
            const float b20 = (col     < T) ? g_b2[toff + col]     : 0.0f;
            const float b21 = (col + 1 < T) ? g_b2[toff + col + 1] : 0.0f;
#pragma unroll
            for (int i = 0; i < 4; i++) {
                float v;
                v = acc[i][j][0] * INVWS + b20; acc[i][j][0] = v / (1.0f + __expf(-v)) * WSCALE;
                v = acc[i][j][1] * INVWS + b21; acc[i][j][1] = v / (1.0f + __expf(-v)) * WSCALE;
                v = acc[i][j][2] * INVWS + b20; acc[i][j][2] = v / (1.0f + __expf(-v)) * WSCALE;
                v = acc[i][j][3] * INVWS + b21; acc[i][j][3] = v / (1.0f + __expf(-v)) * WSCALE;
            }
        }
    }

    // ---- pass 2: acc += x @ (wr*256)_seg^T  (K = 1024), same registers ----
    {
        load_tile_async(sb,          g_xf, arow, EMBED, 0, tid, 128);
        load_tile_async(sb + TILE_B, g_wr, brow, EMBED, 0, tid, tmax);
        CP_COMMIT();
    }
    const int nK2 = EMBED / KC;
    for (int ks = 0; ks < nK2; ks++) {
        CP_WAIT0();
        __syncthreads();
        if (ks + 1 < nK2) {
            const uint32_t base = sb + ((ks + 1) & 1) * STAGE_B;
            const int k0 = (ks + 1) * KC;
            load_tile_async(base,          g_xf, arow, EMBED, k0, tid, 128);
            load_tile_async(base + TILE_B, g_wr, brow, EMBED, k0, tid, tmax);
            CP_COMMIT();
        }
        if (active)
            mma_stage(sb + (ks & 1) * STAGE_B, lane, warp_m, warp_n, acc);
    }

    // ---- store: acc/256 + br (cols < T), zeros to max_dim ----
#pragma unroll
    for (int i = 0; i < 4; i++) {
        const int rowA = warp_m * 64 + i * 16 + r0;
#pragma unroll
        for (int j = 0; j < 4; j++) {
            const int col = t0 + warp_n * 32 + j * 8 + c0;
            if (col >= max_dim) continue;
            float2 v0, v1;
            if (col < T) {   // T even, col even -> col+1 < T too
                const float br0 = g_br[toff + col], br1 = g_br[toff + col + 1];
                v0 = make_float2(acc[i][j][0] * INVWS + br0, acc[i][j][1] * INVWS + br1);
                v1 = make_float2(acc[i][j][2] * INVWS + br0, acc[i][j][3] * INVWS + br1);
            } else {
                v0 = make_float2(0.f, 0.f);
                v1 = v0;
            }
            *reinterpret_cast<float2*>(outBase + (size_t)rowA * max_dim + col) = v0;
            *reinterpret_cast<float2*>(outBase + (size_t)(rowA + 8) * max_dim + col) = v1;
        }
    }
}

// ----------------------------------------------------------------------------
extern "C" void kernel_launch(void* const* d_in, const int* in_sizes, int n_in,
                              void* d_out, int out_size)
{
    const float* x     = (const float*)d_in[0];
    const int*   psz   = (const int*)d_in[1];
    const float* W_in  = (const float*)d_in[2];
    const float* b_in  = (const float*)d_in[3];
    const float* W_sh  = (const float*)d_in[4];
    const float* b_sh  = (const float*)d_in[5];
    const float* W_res = (const float*)d_in[6];
    const float* b_res = (const float*)d_in[7];
    float* out = (float*)d_out;

    const int max_dim = out_size / (NSAMP * PTOK);

    cudaFuncSetAttribute(gemm1_kernel, cudaFuncAttributeMaxDynamicSharedMemorySize, SMEM_TOTAL);
    cudaFuncSetAttribute(head_kernel,  cudaFuncAttributeMaxDynamicSharedMemorySize, SMEM_TOTAL);

    // 1) vectorized prep: x/W_in -> fp16 + interpolated head weights + biases
    {
        const long total = ((long)MROWS * EMBED + (long)INTER * EMBED
                          + (long)TTOT * INTER + (long)TTOT * EMBED + 2L * TTOT) / 8;
        prep_kernel<<<(unsigned)((total + 255) / 256), 256>>>(x, W_in, W_sh, b_sh, W_res, b_res);
    }
    // 2) xs = x @ W_in^T + b_in
    {
        dim3 g(INTER / 128, MROWS / 128);   // (32, 256)
        gemm1_kernel<<<g, 256, SMEM_TOTAL>>>(b_in);
    }
    // 3) fused per-sample heads + zero padding
    {
        dim3 g((max_dim + 127) / 128, NSAMP);
        head_kernel<<<g, 256, SMEM_TOTAL>>>(psz, out, max_dim);
    }
}

// round 15
// speedup vs baseline: 1.4660x; 1.0134x over previous
#include <cuda_runtime.h>
#include <cuda_fp16.h>
#include <math.h>
#include <stdint.h>

// ============================================================================
// MultiSizeProjHead via portable mma.sync — single-plane fp16 x fp16 (1 term)
// R15 = R14 winner (64x32 warp tiles, 2 CTAs/SM, KC=64, vectorized prep)
// + ALU diet: strength-reduced loader addressing (no per-chunk 64-bit mul)
// and hoisted LDSM base addresses in the MMA stage.
// Weights pre-scaled x256 (exact); epilogues multiply by 1/256.
// ============================================================================
#define EMBED   1024
#define INTER   4096
#define SBASE   672
#define OUTD    21
#define NSAMP   256
#define PTOK    128
#define MROWS   (NSAMP * PTOK)
#define TTOT    2520        // 168 + 336 + 672 + 1344

#define KC       64                  // K per SMEM stage
#define TSTRIDE  144                 // bytes per smem row: 64 fp16 + 16 pad
#define TILE_B   (128 * TSTRIDE)     // 18432 bytes per 128x64 tile
#define STAGE_B  (2 * TILE_B)        // A, B = 36864
#define SMEM_TOTAL (2 * STAGE_B)     // double buffered: 73728 B

#define WSCALE   256.0f
#define INVWS    0.00390625f         // 1/256

__device__ __constant__ int c_T[4]    = {168, 336, 672, 1344};
__device__ __constant__ int c_Toff[4] = {0, 168, 504, 1176};

// ---------------- device scratch (no runtime allocation allowed) -----------
__device__ __half g_xf [(size_t)MROWS * EMBED];     // x, fp16
__device__ __half g_wi [(size_t)INTER * EMBED];     // W_in*256, fp16
__device__ __half g_xsf[(size_t)MROWS * INTER];     // xs, fp16
__device__ __half g_w2 [(size_t)TTOT * INTER];      // interp W_shared^T *256, t-major
__device__ __half g_wr [(size_t)TTOT * EMBED];      // interp W_res^T *256, t-major
__device__ float g_b2[TTOT];
__device__ float g_br[TTOT];

// ---------------- portable PTX helpers -------------------------------------
__device__ __forceinline__ uint32_t smem_to_u32(const void* p) {
    uint32_t a;
    asm("{ .reg .u64 t; cvta.to.shared.u64 t, %1; cvt.u32.u64 %0, t; }" : "=r"(a) : "l"(p));
    return a;
}
__device__ __forceinline__ void cp_async16(uint32_t dst, const void* src, uint32_t src_bytes) {
    asm volatile("cp.async.cg.shared.global [%0], [%1], 16, %2;"
                 :: "r"(dst), "l"(src), "r"(src_bytes) : "memory");
}
#define CP_COMMIT() asm volatile("cp.async.commit_group;" ::: "memory")
#define CP_WAIT0()  asm volatile("cp.async.wait_group 0;" ::: "memory")

__device__ __forceinline__ void ldsm_x4(uint32_t* r, uint32_t addr) {
    asm volatile("ldmatrix.sync.aligned.m8n8.x4.shared.b16 {%0,%1,%2,%3}, [%4];"
                 : "=r"(r[0]), "=r"(r[1]), "=r"(r[2]), "=r"(r[3]) : "r"(addr));
}
__device__ __forceinline__ void mma16816(float* c, const uint32_t* a, uint32_t b0, uint32_t b1) {
    asm volatile("mma.sync.aligned.m16n8k16.row.col.f32.f16.f16.f32 "
                 "{%0,%1,%2,%3}, {%4,%5,%6,%7}, {%8,%9}, {%0,%1,%2,%3};"
                 : "+f"(c[0]), "+f"(c[1]), "+f"(c[2]), "+f"(c[3])
                 : "r"(a[0]), "r"(a[1]), "r"(a[2]), "r"(a[3]), "r"(b0), "r"(b1));
}
__device__ __forceinline__ uint32_t pack2h(__half a, __half b) {
    return (uint32_t)__half_as_ushort(a) | ((uint32_t)__half_as_ushort(b) << 16);
}
// pack 8 scaled floats (two float4) into 8 fp16
__device__ __forceinline__ uint4 cvt8(float4 a, float4 b, float s) {
    uint4 r;
    r.x = pack2h(__float2half_rn(a.x * s), __float2half_rn(a.y * s));
    r.y = pack2h(__float2half_rn(a.z * s), __float2half_rn(a.w * s));
    r.z = pack2h(__float2half_rn(b.x * s), __float2half_rn(b.y * s));
    r.w = pack2h(__float2half_rn(b.z * s), __float2half_rn(b.w * s));
    return r;
}

// async-load one 128x64 fp16 tile (rows padded to 144B); rows >= vrows zero-fill.
// Strength-reduced: one pointer, advanced by 32*stride per iteration.
__device__ __forceinline__ void load_tile_async(uint32_t sdst, const __half* __restrict__ src,
                                                long row0, long stride, int k0, int tid, int vrows) {
    const int r0 = tid >> 3, c8 = tid & 7;
    const __half* p = src + (row0 + r0) * stride + k0 + (c8 << 3);
    const __half* const pSafe = src + row0 * stride + k0 + (c8 << 3);
    uint32_t d = sdst + (uint32_t)(r0 * TSTRIDE + c8 * 16);
#pragma unroll
    for (int i = 0; i < 4; i++) {
        const bool ok = (r0 + i * 32) < vrows;
        cp_async16(d, ok ? p : pSafe, ok ? 16u : 0u);
        p += 32 * stride;
        d += 32 * TSTRIDE;
    }
}

// one KC=64 stage of 1-term MMA: acc += A*B   (warp tile 64x32)
// Hoisted bases: per-k16 addresses are base + compile-time constants.
__device__ __forceinline__ void mma_stage(uint32_t base, int lane, int warp_m, int warp_n,
                                          float acc[4][4][4]) {
    const int lr = lane & 7, lg = lane >> 3;
    const int rowSel = ((lg & 1) << 3) + lr;
    const int colHalf = (lg >> 1) << 3;
    const uint32_t aBase = base + (uint32_t)((warp_m * 64 + rowSel) * TSTRIDE + colHalf * 2);
    const uint32_t bBase = base + TILE_B + (uint32_t)((warp_n * 32 + rowSel) * TSTRIDE + colHalf * 2);
#pragma unroll
    for (int k16 = 0; k16 < KC; k16 += 16) {
        const uint32_t colOff = (uint32_t)(k16 * 2);
        uint32_t a[4][4], b[2][4];
#pragma unroll
        for (int i = 0; i < 4; i++)
            ldsm_x4(a[i], aBase + (uint32_t)(i * 16 * TSTRIDE) + colOff);
#pragma unroll
        for (int jj = 0; jj < 2; jj++)
            ldsm_x4(b[jj], bBase + (uint32_t)(jj * 16 * TSTRIDE) + colOff);
#pragma unroll
        for (int i = 0; i < 4; i++)
#pragma unroll
            for (int j = 0; j < 4; j++)
                mma16816(acc[i][j], a[i], b[j >> 1][j & 1], b[j >> 1][(j & 1) + 2]);
    }
}

// ---------------- vectorized prep: 8 contiguous elements per thread --------
__device__ __forceinline__ void interp_coef(int tg, int& i0, int& i1, float& lam) {
    const int s = (tg < 168) ? 0 : (tg < 504) ? 1 : (tg < 1176) ? 2 : 3;
    const int t = tg - c_Toff[s];
    const float scale = (float)SBASE / (float)c_T[s];
    float src = fmaxf(((float)t + 0.5f) * scale - 0.5f, 0.0f);
    i0 = (int)src;                  // src >= 0 -> trunc == floor
    if (i0 > SBASE - 1) i0 = SBASE - 1;
    i1 = min(i0 + 1, SBASE - 1);
    lam = src - (float)i0;
}
// exact reference rounding: w0*(1-lam) + w1*lam
__device__ __forceinline__ float4 mix4(float4 a, float4 b, float lam) {
    const float om = 1.0f - lam;
    return make_float4(a.x * om + b.x * lam, a.y * om + b.y * lam,
                       a.z * om + b.z * lam, a.w * om + b.w * lam);
}

__global__ void prep_kernel(const float* __restrict__ x, const float* __restrict__ W_in,
                            const float* __restrict__ Ws, const float* __restrict__ bs,
                            const float* __restrict__ Wr, const float* __restrict__ brs) {
    const long nx8 = (long)MROWS * EMBED / 8;
    const long nw8 = (long)INTER * EMBED / 8;
    const long n28 = (long)TTOT * INTER / 8;
    const long nr8 = (long)TTOT * EMBED / 8;
    const long nb8 = TTOT / 8;                 // 315
    const long total = nx8 + nw8 + n28 + nr8 + 2 * nb8;
    const long i = blockIdx.x * (long)blockDim.x + threadIdx.x;
    if (i >= total) return;

    if (i < nx8) {
        const long e = i * 8;
        const float4 a = *(const float4*)(x + e);
        const float4 b = *(const float4*)(x + e + 4);
        *(uint4*)(g_xf + e) = cvt8(a, b, 1.0f);
    } else if (i < nx8 + nw8) {
        const long e = (i - nx8) * 8;
        const float4 a = *(const float4*)(W_in + e);
        const float4 b = *(const float4*)(W_in + e + 4);
        *(uint4*)(g_wi + e) = cvt8(a, b, WSCALE);
    } else if (i < nx8 + nw8 + n28) {
        const long e = (i - nx8 - nw8) * 8;
        const int t = (int)(e / INTER), k = (int)(e % INTER);
        int i0, i1; float lam;
        interp_coef(t, i0, i1, lam);
        const float4 a0 = *(const float4*)(Ws + (long)i0 * INTER + k);
        const float4 a1 = *(const float4*)(Ws + (long)i0 * INTER + k + 4);
        const float4 b0 = *(const float4*)(Ws + (long)i1 * INTER + k);
        const float4 b1 = *(const float4*)(Ws + (long)i1 * INTER + k + 4);
        *(uint4*)(g_w2 + e) = cvt8(mix4(a0, b0, lam), mix4(a1, b1, lam), WSCALE);
    } else if (i < nx8 + nw8 + n28 + nr8) {
        const long e = (i - nx8 - nw8 - n28) * 8;
        const int t = (int)(e / EMBED), k = (int)(e % EMBED);
        int i0, i1; float lam;
        interp_coef(t, i0, i1, lam);
        const float4 a0 = *(const float4*)(Wr + (long)i0 * EMBED + k);
        const float4 a1 = *(const float4*)(Wr + (long)i0 * EMBED + k + 4);
        const float4 b0 = *(const float4*)(Wr + (long)i1 * EMBED + k);
        const float4 b1 = *(const float4*)(Wr + (long)i1 * EMBED + k + 4);
        *(uint4*)(g_wr + e) = cvt8(mix4(a0, b0, lam), mix4(a1, b1, lam), WSCALE);
    } else if (i < nx8 + nw8 + n28 + nr8 + nb8) {
        const int t0 = (int)(i - nx8 - nw8 - n28 - nr8) * 8;
#pragma unroll
        for (int u = 0; u < 8; u++) {
            int i0, i1; float lam;
            interp_coef(t0 + u, i0, i1, lam);
            g_b2[t0 + u] = bs[i0] * (1.0f - lam) + bs[i1] * lam;
        }
    } else {
        const int t0 = (int)(i - nx8 - nw8 - n28 - nr8 - nb8) * 8;
#pragma unroll
        for (int u = 0; u < 8; u++) {
            int i0, i1; float lam;
            interp_coef(t0 + u, i0, i1, lam);
            g_br[t0 + u] = brs[i0] * (1.0f - lam) + brs[i1] * lam;
        }
    }
}

// ---------------- GEMM1: xs = x @ W_in^T + b_in ------------------------------
__global__ void __launch_bounds__(256, 2)
gemm1_kernel(const float* __restrict__ b_in) {
    extern __shared__ char smem[];
    const uint32_t sb = smem_to_u32(smem);
    const int tid = threadIdx.x;
    const int lane = tid & 31, wid = tid >> 5;
    const int warp_m = wid >> 2, warp_n = wid & 3;
    const long bm = (long)blockIdx.y * 128;
    const long bn = (long)blockIdx.x * 128;

    float acc[4][4][4];
#pragma unroll
    for (int i = 0; i < 4; i++)
#pragma unroll
        for (int j = 0; j < 4; j++)
#pragma unroll
            for (int e = 0; e < 4; e++) acc[i][j][e] = 0.0f;

    {
        load_tile_async(sb,          g_xf, bm, EMBED, 0, tid, 128);
        load_tile_async(sb + TILE_B, g_wi, bn, EMBED, 0, tid, 128);
        CP_COMMIT();
    }
    const int nK = EMBED / KC;
    for (int ks = 0; ks < nK; ks++) {
        CP_WAIT0();
        __syncthreads();
        if (ks + 1 < nK) {
            const uint32_t base = sb + ((ks + 1) & 1) * STAGE_B;
            const int k0 = (ks + 1) * KC;
            load_tile_async(base,          g_xf, bm, EMBED, k0, tid, 128);
            load_tile_async(base + TILE_B, g_wi, bn, EMBED, k0, tid, 128);
            CP_COMMIT();
        }
        mma_stage(sb + (ks & 1) * STAGE_B, lane, warp_m, warp_n, acc);
    }

    // epilogue: acc/256 + b_in -> fp16 single plane
    const int r0 = lane >> 2;
    const int c0 = (lane & 3) * 2;
#pragma unroll
    for (int i = 0; i < 4; i++) {
        const long rowA = bm + warp_m * 64 + i * 16 + r0;
        const long rowB = rowA + 8;
#pragma unroll
        for (int j = 0; j < 4; j++) {
            const long col = bn + warp_n * 32 + j * 8 + c0;
            const float bi0 = b_in[col], bi1 = b_in[col + 1];
            *(uint32_t*)(g_xsf + rowA * INTER + col) =
                pack2h(__float2half_rn(acc[i][j][0] * INVWS + bi0),
                       __float2half_rn(acc[i][j][1] * INVWS + bi1));
            *(uint32_t*)(g_xsf + rowB * INTER + col) =
                pack2h(__float2half_rn(acc[i][j][2] * INVWS + bi0),
                       __float2half_rn(acc[i][j][3] * INVWS + bi1));
        }
    }
}

// ---------------- head kernel: silu(xs@w2+b2) + x@wr+br + padding ----------
// Single accumulator bank: silu output rescaled x256 so pass-2 (weights x256)
// accumulates in place; store multiplies by 1/256. Tail warps (fully past
// tmax) skip LDSM+MMA; their acc is never stored.
__global__ void __launch_bounds__(256, 2)
head_kernel(const int* __restrict__ psz, float* __restrict__ out, int max_dim) {
    const int n  = blockIdx.y;
    const int t0 = blockIdx.x * 128;
    const int tid = threadIdx.x;

    const int ps = psz[n];
    const int T = ps * OUTD;
    const int s4 = (ps == 8) ? 0 : (ps == 16) ? 1 : (ps == 32) ? 2 : 3;
    const int toff = c_Toff[s4];
    float* outBase = out + (size_t)n * PTOK * max_dim;

    if (t0 >= T) {  // pure zero-pad tile
        const int colq = min(128, max_dim - t0) >> 2;
        const float4 z = make_float4(0.f, 0.f, 0.f, 0.f);
        for (int idx = tid; idx < PTOK * colq; idx += 256) {
            const int r = idx / colq, c = idx % colq;
            *reinterpret_cast<float4*>(outBase + (size_t)r * max_dim + t0 + c * 4) = z;
        }
        return;
    }

    extern __shared__ char smem[];
    const uint32_t sb = smem_to_u32(smem);
    const int lane = tid & 31, wid = tid >> 5;
    const int warp_m = wid >> 2, warp_n = wid & 3;

    const int tmax = min(T - t0, 128);
    const bool active = (warp_n * 32 < tmax);
    const long arow = (long)n * PTOK;
    const long brow = (long)toff + t0;

    float acc[4][4][4];
#pragma unroll
    for (int i = 0; i < 4; i++)
#pragma unroll
        for (int j = 0; j < 4; j++)
#pragma unroll
            for (int e = 0; e < 4; e++) acc[i][j][e] = 0.0f;

    const int r0 = lane >> 2;
    const int c0 = (lane & 3) * 2;

    // ---- pass 1: lin = xs @ w2_seg^T  (K = 4096) ----
    {
        load_tile_async(sb,          g_xsf, arow, INTER, 0, tid, 128);
        load_tile_async(sb + TILE_B, g_w2,  brow, INTER, 0, tid, tmax);
        CP_COMMIT();
    }
    const int nK1 = INTER / KC;
    for (int ks = 0; ks < nK1; ks++) {
        CP_WAIT0();
        __syncthreads();
        if (ks + 1 < nK1) {
            const uint32_t base = sb + ((ks + 1) & 1) * STAGE_B;
            const int k0 = (ks + 1) * KC;
            load_tile_async(base,          g_xsf, arow, INTER, k0, tid, 128);
            load_tile_async(base + TILE_B, g_w2,  brow, INTER, k0, tid, tmax);
            CP_COMMIT();
        }
        if (active)
            mma_stage(sb + (ks & 1) * STAGE_B, lane, warp_m, warp_n, acc);
    }

    // ---- silu(acc/256 + b2), rescaled x256 so pass 2 accumulates in place --
    if (active) {
#pragma unroll
        for (int j = 0; j < 4; j++) {
            const int col = t0 + warp_n * 32 + j * 8 + c0;
            const float b20 = (col     < T) ? g_b2[toff + col]     : 0.0f;
            const float b21 = (col + 1 < T) ? g_b2[toff + col + 1] : 0.0f;
#pragma unroll
            for (int i = 0; i < 4; i++) {
                float v;
                v = acc[i][j][0] * INVWS + b20; acc[i][j][0] = v / (1.0f + __expf(-v)) * WSCALE;
                v = acc[i][j][1] * INVWS + b21; acc[i][j][1] = v / (1.0f + __expf(-v)) * WSCALE;
                v = acc[i][j][2] * INVWS + b20; acc[i][j][2] = v / (1.0f + __expf(-v)) * WSCALE;
                v = acc[i][j][3] * INVWS + b21; acc[i][j][3] = v / (1.0f + __expf(-v)) * WSCALE;
            }
        }
    }

    // ---- pass 2: acc += x @ (wr*256)_seg^T  (K = 1024), same registers ----
    {
        load_tile_async(sb,          g_xf, arow, EMBED, 0, tid, 128);
        load_tile_async(sb + TILE_B, g_wr, brow, EMBED, 0, tid, tmax);
        CP_COMMIT();
    }
    const int nK2 = EMBED / KC;
    for (int ks = 0; ks < nK2; ks++) {
        CP_WAIT0();
        __syncthreads();
        if (ks + 1 < nK2) {
            const uint32_t base = sb + ((ks + 1) & 1) * STAGE_B;
            const int k0 = (ks + 1) * KC;
            load_tile_async(base,          g_xf, arow, EMBED, k0, tid, 128);
            load_tile_async(base + TILE_B, g_wr, brow, EMBED, k0, tid, tmax);
            CP_COMMIT();
        }
        if (active)
            mma_stage(sb + (ks & 1) * STAGE_B, lane, warp_m, warp_n, acc);
    }

    // ---- store: acc/256 + br (cols < T), zeros to max_dim ----
#pragma unroll
    for (int i = 0; i < 4; i++) {
        const int rowA = warp_m * 64 + i * 16 + r0;
#pragma unroll
        for (int j = 0; j < 4; j++) {
            const int col = t0 + warp_n * 32 + j * 8 + c0;
            if (col >= max_dim) continue;
            float2 v0, v1;
            if (col < T) {   // T even, col even -> col+1 < T too
                const float br0 = g_br[toff + col], br1 = g_br[toff + col + 1];
                v0 = make_float2(acc[i][j][0] * INVWS + br0, acc[i][j][1] * INVWS + br1);
                v1 = make_float2(acc[i][j][2] * INVWS + br0, acc[i][j][3] * INVWS + br1);
            } else {
                v0 = make_float2(0.f, 0.f);
                v1 = v0;
            }
            *reinterpret_cast<float2*>(outBase + (size_t)rowA * max_dim + col) = v0;
            *reinterpret_cast<float2*>(outBase + (size_t)(rowA + 8) * max_dim + col) = v1;
        }
    }
}

// ----------------------------------------------------------------------------
extern "C" void kernel_launch(void* const* d_in, const int* in_sizes, int n_in,
                              void* d_out, int out_size)
{
    const float* x     = (const float*)d_in[0];
    const int*   psz   = (const int*)d_in[1];
    const float* W_in  = (const float*)d_in[2];
    const float* b_in  = (const float*)d_in[3];
    const float* W_sh  = (const float*)d_in[4];
    const float* b_sh  = (const float*)d_in[5];
    const float* W_res = (const float*)d_in[6];
    const float* b_res = (const float*)d_in[7];
    float* out = (float*)d_out;

    const int max_dim = out_size / (NSAMP * PTOK);

    cudaFuncSetAttribute(gemm1_kernel, cudaFuncAttributeMaxDynamicSharedMemorySize, SMEM_TOTAL);
    cudaFuncSetAttribute(head_kernel,  cudaFuncAttributeMaxDynamicSharedMemorySize, SMEM_TOTAL);

    // 1) vectorized prep: x/W_in -> fp16 + interpolated head weights + biases
    {
        const long total = ((long)MROWS * EMBED + (long)INTER * EMBED
                          + (long)TTOT * INTER + (long)TTOT * EMBED + 2L * TTOT) / 8;
        prep_kernel<<<(unsigned)((total + 255) / 256), 256>>>(x, W_in, W_sh, b_sh, W_res, b_res);
    }
    // 2) xs = x @ W_in^T + b_in
    {
        dim3 g(INTER / 128, MROWS / 128);   // (32, 256)
        gemm1_kernel<<<g, 256, SMEM_TOTAL>>>(b_in);
    }
    // 3) fused per-sample heads + zero padding
    {
        dim3 g((max_dim + 127) / 128, NSAMP);
        head_kernel<<<g, 256, SMEM_TOTAL>>>(psz, out, max_dim);
    }
}

// round 16
// speedup vs baseline: 1.4685x; 1.0017x over previous
#include <cuda_runtime.h>
#include <cuda_fp16.h>
#include <math.h>
#include <stdint.h>

// ============================================================================
// MultiSizeProjHead via portable mma.sync — single-plane fp16 x fp16 (1 term)
// R16 = R15 winner (64x32 warp tiles, 2 CTAs/SM, KC=64, vectorized prep,
// strength-reduced addressing) + persistent head CTAs pulling tiles from an
// atomic queue, t-major (heavy-first) order for tail packing.
// Weights pre-scaled x256 (exact); epilogues multiply by 1/256.
// ============================================================================
#define EMBED   1024
#define INTER   4096
#define SBASE   672
#define OUTD    21
#define NSAMP   256
#define PTOK    128
#define MROWS   (NSAMP * PTOK)
#define TTOT    2520        // 168 + 336 + 672 + 1344

#define KC       64                  // K per SMEM stage
#define TSTRIDE  144                 // bytes per smem row: 64 fp16 + 16 pad
#define TILE_B   (128 * TSTRIDE)     // 18432 bytes per 128x64 tile
#define STAGE_B  (2 * TILE_B)        // A, B = 36864
#define SMEM_TOTAL (2 * STAGE_B)     // double buffered: 73728 B

#define WSCALE   256.0f
#define INVWS    0.00390625f         // 1/256
#define NPERS    296                 // persistent head CTAs (2 x 148)

__device__ __constant__ int c_T[4]    = {168, 336, 672, 1344};
__device__ __constant__ int c_Toff[4] = {0, 168, 504, 1176};

// ---------------- device scratch (no runtime allocation allowed) -----------
__device__ __half g_xf [(size_t)MROWS * EMBED];     // x, fp16
__device__ __half g_wi [(size_t)INTER * EMBED];     // W_in*256, fp16
__device__ __half g_xsf[(size_t)MROWS * INTER];     // xs, fp16
__device__ __half g_w2 [(size_t)TTOT * INTER];      // interp W_shared^T *256, t-major
__device__ __half g_wr [(size_t)TTOT * EMBED];      // interp W_res^T *256, t-major
__device__ float g_b2[TTOT];
__device__ float g_br[TTOT];
__device__ int   g_ctr;                             // head work-queue counter

// ---------------- portable PTX helpers -------------------------------------
__device__ __forceinline__ uint32_t smem_to_u32(const void* p) {
    uint32_t a;
    asm("{ .reg .u64 t; cvta.to.shared.u64 t, %1; cvt.u32.u64 %0, t; }" : "=r"(a) : "l"(p));
    return a;
}
__device__ __forceinline__ void cp_async16(uint32_t dst, const void* src, uint32_t src_bytes) {
    asm volatile("cp.async.cg.shared.global [%0], [%1], 16, %2;"
                 :: "r"(dst), "l"(src), "r"(src_bytes) : "memory");
}
#define CP_COMMIT() asm volatile("cp.async.commit_group;" ::: "memory")
#define CP_WAIT0()  asm volatile("cp.async.wait_group 0;" ::: "memory")

__device__ __forceinline__ void ldsm_x4(uint32_t* r, uint32_t addr) {
    asm volatile("ldmatrix.sync.aligned.m8n8.x4.shared.b16 {%0,%1,%2,%3}, [%4];"
                 : "=r"(r[0]), "=r"(r[1]), "=r"(r[2]), "=r"(r[3]) : "r"(addr));
}
__device__ __forceinline__ void mma16816(float* c, const uint32_t* a, uint32_t b0, uint32_t b1) {
    asm volatile("mma.sync.aligned.m16n8k16.row.col.f32.f16.f16.f32 "
                 "{%0,%1,%2,%3}, {%4,%5,%6,%7}, {%8,%9}, {%0,%1,%2,%3};"
                 : "+f"(c[0]), "+f"(c[1]), "+f"(c[2]), "+f"(c[3])
                 : "r"(a[0]), "r"(a[1]), "r"(a[2]), "r"(a[3]), "r"(b0), "r"(b1));
}
__device__ __forceinline__ uint32_t pack2h(__half a, __half b) {
    return (uint32_t)__half_as_ushort(a) | ((uint32_t)__half_as_ushort(b) << 16);
}
__device__ __forceinline__ uint4 cvt8(float4 a, float4 b, float s) {
    uint4 r;
    r.x = pack2h(__float2half_rn(a.x * s), __float2half_rn(a.y * s));
    r.y = pack2h(__float2half_rn(a.z * s), __float2half_rn(a.w * s));
    r.z = pack2h(__float2half_rn(b.x * s), __float2half_rn(b.y * s));
    r.w = pack2h(__float2half_rn(b.z * s), __float2half_rn(b.w * s));
    return r;
}

// async-load one 128x64 fp16 tile (rows padded to 144B); rows >= vrows zero-fill
__device__ __forceinline__ void load_tile_async(uint32_t sdst, const __half* __restrict__ src,
                                                long row0, long stride, int k0, int tid, int vrows) {
    const int r0 = tid >> 3, c8 = tid & 7;
    const __half* p = src + (row0 + r0) * stride + k0 + (c8 << 3);
    const __half* const pSafe = src + row0 * stride + k0 + (c8 << 3);
    uint32_t d = sdst + (uint32_t)(r0 * TSTRIDE + c8 * 16);
#pragma unroll
    for (int i = 0; i < 4; i++) {
        const bool ok = (r0 + i * 32) < vrows;
        cp_async16(d, ok ? p : pSafe, ok ? 16u : 0u);
        p += 32 * stride;
        d += 32 * TSTRIDE;
    }
}

// one KC=64 stage of 1-term MMA: acc += A*B   (warp tile 64x32)
__device__ __forceinline__ void mma_stage(uint32_t base, int lane, int warp_m, int warp_n,
                                          float acc[4][4][4]) {
    const int lr = lane & 7, lg = lane >> 3;
    const int rowSel = ((lg & 1) << 3) + lr;
    const int colHalf = (lg >> 1) << 3;
    const uint32_t aBase = base + (uint32_t)((warp_m * 64 + rowSel) * TSTRIDE + colHalf * 2);
    const uint32_t bBase = base + TILE_B + (uint32_t)((warp_n * 32 + rowSel) * TSTRIDE + colHalf * 2);
#pragma unroll
    for (int k16 = 0; k16 < KC; k16 += 16) {
        const uint32_t colOff = (uint32_t)(k16 * 2);
        uint32_t a[4][4], b[2][4];
#pragma unroll
        for (int i = 0; i < 4; i++)
            ldsm_x4(a[i], aBase + (uint32_t)(i * 16 * TSTRIDE) + colOff);
#pragma unroll
        for (int jj = 0; jj < 2; jj++)
            ldsm_x4(b[jj], bBase + (uint32_t)(jj * 16 * TSTRIDE) + colOff);
#pragma unroll
        for (int i = 0; i < 4; i++)
#pragma unroll
            for (int j = 0; j < 4; j++)
                mma16816(acc[i][j], a[i], b[j >> 1][j & 1], b[j >> 1][(j & 1) + 2]);
    }
}

// ---------------- vectorized prep: 8 contiguous elements per thread --------
__device__ __forceinline__ void interp_coef(int tg, int& i0, int& i1, float& lam) {
    const int s = (tg < 168) ? 0 : (tg < 504) ? 1 : (tg < 1176) ? 2 : 3;
    const int t = tg - c_Toff[s];
    const float scale = (float)SBASE / (float)c_T[s];
    float src = fmaxf(((float)t + 0.5f) * scale - 0.5f, 0.0f);
    i0 = (int)src;
    if (i0 > SBASE - 1) i0 = SBASE - 1;
    i1 = min(i0 + 1, SBASE - 1);
    lam = src - (float)i0;
}
__device__ __forceinline__ float4 mix4(float4 a, float4 b, float lam) {
    const float om = 1.0f - lam;
    return make_float4(a.x * om + b.x * lam, a.y * om + b.y * lam,
                       a.z * om + b.z * lam, a.w * om + b.w * lam);
}

__global__ void prep_kernel(const float* __restrict__ x, const float* __restrict__ W_in,
                            const float* __restrict__ Ws, const float* __restrict__ bs,
                            const float* __restrict__ Wr, const float* __restrict__ brs) {
    if (blockIdx.x == 0 && threadIdx.x == 0) g_ctr = 0;   // reset head work queue
    const long nx8 = (long)MROWS * EMBED / 8;
    const long nw8 = (long)INTER * EMBED / 8;
    const long n28 = (long)TTOT * INTER / 8;
    const long nr8 = (long)TTOT * EMBED / 8;
    const long nb8 = TTOT / 8;                 // 315
    const long total = nx8 + nw8 + n28 + nr8 + 2 * nb8;
    const long i = blockIdx.x * (long)blockDim.x + threadIdx.x;
    if (i >= total) return;

    if (i < nx8) {
        const long e = i * 8;
        const float4 a = *(const float4*)(x + e);
        const float4 b = *(const float4*)(x + e + 4);
        *(uint4*)(g_xf + e) = cvt8(a, b, 1.0f);
    } else if (i < nx8 + nw8) {
        const long e = (i - nx8) * 8;
        const float4 a = *(const float4*)(W_in + e);
        const float4 b = *(const float4*)(W_in + e + 4);
        *(uint4*)(g_wi + e) = cvt8(a, b, WSCALE);
    } else if (i < nx8 + nw8 + n28) {
        const long e = (i - nx8 - nw8) * 8;
        const int t = (int)(e / INTER), k = (int)(e % INTER);
        int i0, i1; float lam;
        interp_coef(t, i0, i1, lam);
        const float4 a0 = *(const float4*)(Ws + (long)i0 * INTER + k);
        const float4 a1 = *(const float4*)(Ws + (long)i0 * INTER + k + 4);
        const float4 b0 = *(const float4*)(Ws + (long)i1 * INTER + k);
        const float4 b1 = *(const float4*)(Ws + (long)i1 * INTER + k + 4);
        *(uint4*)(g_w2 + e) = cvt8(mix4(a0, b0, lam), mix4(a1, b1, lam), WSCALE);
    } else if (i < nx8 + nw8 + n28 + nr8) {
        const long e = (i - nx8 - nw8 - n28) * 8;
        const int t = (int)(e / EMBED), k = (int)(e % EMBED);
        int i0, i1; float lam;
        interp_coef(t, i0, i1, lam);
        const float4 a0 = *(const float4*)(Wr + (long)i0 * EMBED + k);
        const float4 a1 = *(const float4*)(Wr + (long)i0 * EMBED + k + 4);
        const float4 b0 = *(const float4*)(Wr + (long)i1 * EMBED + k);
        const float4 b1 = *(const float4*)(Wr + (long)i1 * EMBED + k + 4);
        *(uint4*)(g_wr + e) = cvt8(mix4(a0, b0, lam), mix4(a1, b1, lam), WSCALE);
    } else if (i < nx8 + nw8 + n28 + nr8 + nb8) {
        const int t0 = (int)(i - nx8 - nw8 - n28 - nr8) * 8;
#pragma unroll
        for (int u = 0; u < 8; u++) {
            int i0, i1; float lam;
            interp_coef(t0 + u, i0, i1, lam);
            g_b2[t0 + u] = bs[i0] * (1.0f - lam) + bs[i1] * lam;
        }
    } else {
        const int t0 = (int)(i - nx8 - nw8 - n28 - nr8 - nb8) * 8;
#pragma unroll
        for (int u = 0; u < 8; u++) {
            int i0, i1; float lam;
            interp_coef(t0 + u, i0, i1, lam);
            g_br[t0 + u] = brs[i0] * (1.0f - lam) + brs[i1] * lam;
        }
    }
}

// ---------------- GEMM1: xs = x @ W_in^T + b_in ------------------------------
__global__ void __launch_bounds__(256, 2)
gemm1_kernel(const float* __restrict__ b_in) {
    extern __shared__ char smem[];
    const uint32_t sb = smem_to_u32(smem);
    const int tid = threadIdx.x;
    const int lane = tid & 31, wid = tid >> 5;
    const int warp_m = wid >> 2, warp_n = wid & 3;
    const long bm = (long)blockIdx.y * 128;
    const long bn = (long)blockIdx.x * 128;

    float acc[4][4][4];
#pragma unroll
    for (int i = 0; i < 4; i++)
#pragma unroll
        for (int j = 0; j < 4; j++)
#pragma unroll
            for (int e = 0; e < 4; e++) acc[i][j][e] = 0.0f;

    {
        load_tile_async(sb,          g_xf, bm, EMBED, 0, tid, 128);
        load_tile_async(sb + TILE_B, g_wi, bn, EMBED, 0, tid, 128);
        CP_COMMIT();
    }
    const int nK = EMBED / KC;
    for (int ks = 0; ks < nK; ks++) {
        CP_WAIT0();
        __syncthreads();
        if (ks + 1 < nK) {
            const uint32_t base = sb + ((ks + 1) & 1) * STAGE_B;
            const int k0 = (ks + 1) * KC;
            load_tile_async(base,          g_xf, bm, EMBED, k0, tid, 128);
            load_tile_async(base + TILE_B, g_wi, bn, EMBED, k0, tid, 128);
            CP_COMMIT();
        }
        mma_stage(sb + (ks & 1) * STAGE_B, lane, warp_m, warp_n, acc);
    }

    // epilogue: acc/256 + b_in -> fp16 single plane
    const int r0 = lane >> 2;
    const int c0 = (lane & 3) * 2;
#pragma unroll
    for (int i = 0; i < 4; i++) {
        const long rowA = bm + warp_m * 64 + i * 16 + r0;
        const long rowB = rowA + 8;
#pragma unroll
        for (int j = 0; j < 4; j++) {
            const long col = bn + warp_n * 32 + j * 8 + c0;
            const float bi0 = b_in[col], bi1 = b_in[col + 1];
            *(uint32_t*)(g_xsf + rowA * INTER + col) =
                pack2h(__float2half_rn(acc[i][j][0] * INVWS + bi0),
                       __float2half_rn(acc[i][j][1] * INVWS + bi1));
            *(uint32_t*)(g_xsf + rowB * INTER + col) =
                pack2h(__float2half_rn(acc[i][j][2] * INVWS + bi0),
                       __float2half_rn(acc[i][j][3] * INVWS + bi1));
        }
    }
}

// ---------------- persistent head kernel ------------------------------------
// 296 CTAs pull tiles from g_ctr. Work index w: t-major (heavy tiles first):
//   tblk = w / NSAMP (0..ntb-1), n = w % NSAMP, t0 = tblk*128.
// Inner tile code identical to R15.
__global__ void __launch_bounds__(256, 2)
head_kernel(const int* __restrict__ psz, float* __restrict__ out, int max_dim, int ntiles) {
    extern __shared__ char smem[];
    __shared__ int s_w;
    const uint32_t sb = smem_to_u32(smem);
    const int tid = threadIdx.x;
    const int lane = tid & 31, wid = tid >> 5;
    const int warp_m = wid >> 2, warp_n = wid & 3;
    const int r0 = lane >> 2;
    const int c0 = (lane & 3) * 2;

    while (true) {
        __syncthreads();                       // smem buffers + s_w safe to reuse
        if (tid == 0) s_w = atomicAdd(&g_ctr, 1);
        __syncthreads();
        const int w = s_w;
        if (w >= ntiles) break;

        const int n  = w % NSAMP;
        const int t0 = (w / NSAMP) * 128;

        const int ps = psz[n];
        const int T = ps * OUTD;
        const int s4 = (ps == 8) ? 0 : (ps == 16) ? 1 : (ps == 32) ? 2 : 3;
        const int toff = c_Toff[s4];
        float* outBase = out + (size_t)n * PTOK * max_dim;

        if (t0 >= T) {  // pure zero-pad tile
            const int colq = min(128, max_dim - t0) >> 2;
            const float4 z = make_float4(0.f, 0.f, 0.f, 0.f);
            for (int idx = tid; idx < PTOK * colq; idx += 256) {
                const int r = idx / colq, c = idx % colq;
                *reinterpret_cast<float4*>(outBase + (size_t)r * max_dim + t0 + c * 4) = z;
            }
            continue;
        }

        const int tmax = min(T - t0, 128);
        const bool active = (warp_n * 32 < tmax);
        const long arow = (long)n * PTOK;
        const long brow = (long)toff + t0;

        float acc[4][4][4];
#pragma unroll
        for (int i = 0; i < 4; i++)
#pragma unroll
            for (int j = 0; j < 4; j++)
#pragma unroll
                for (int e = 0; e < 4; e++) acc[i][j][e] = 0.0f;

        // ---- pass 1: lin = xs @ w2_seg^T  (K = 4096) ----
        {
            load_tile_async(sb,          g_xsf, arow, INTER, 0, tid, 128);
            load_tile_async(sb + TILE_B, g_w2,  brow, INTER, 0, tid, tmax);
            CP_COMMIT();
        }
        const int nK1 = INTER / KC;
        for (int ks = 0; ks < nK1; ks++) {
            CP_WAIT0();
            __syncthreads();
            if (ks + 1 < nK1) {
                const uint32_t base = sb + ((ks + 1) & 1) * STAGE_B;
                const int k0 = (ks + 1) * KC;
                load_tile_async(base,          g_xsf, arow, INTER, k0, tid, 128);
                load_tile_async(base + TILE_B, g_w2,  brow, INTER, k0, tid, tmax);
                CP_COMMIT();
            }
            if (active)
                mma_stage(sb + (ks & 1) * STAGE_B, lane, warp_m, warp_n, acc);
        }

        // ---- silu(acc/256 + b2), rescaled x256 for in-place pass 2 ----
        if (active) {
#pragma unroll
            for (int j = 0; j < 4; j++) {
                const int col = t0 + warp_n * 32 + j * 8 + c0;
                const float b20 = (col     < T) ? g_b2[toff + col]     : 0.0f;
                const float b21 = (col + 1 < T) ? g_b2[toff + col + 1] : 0.0f;
#pragma unroll
                for (int i = 0; i < 4; i++) {
                    float v;
                    v = acc[i][j][0] * INVWS + b20; acc[i][j][0] = v / (1.0f + __expf(-v)) * WSCALE;
                    v = acc[i][j][1] * INVWS + b21; acc[i][j][1] = v / (1.0f + __expf(-v)) * WSCALE;
                    v = acc[i][j][2] * INVWS + b20; acc[i][j][2] = v / (1.0f + __expf(-v)) * WSCALE;
                    v = acc[i][j][3] * INVWS + b21; acc[i][j][3] = v / (1.0f + __expf(-v)) * WSCALE;
                }
            }
        }

        // ---- pass 2: acc += x @ (wr*256)_seg^T  (K = 1024) ----
        {
            load_tile_async(sb,          g_xf, arow, EMBED, 0, tid, 128);
            load_tile_async(sb + TILE_B, g_wr, brow, EMBED, 0, tid, tmax);
            CP_COMMIT();
        }
        const int nK2 = EMBED / KC;
        for (int ks = 0; ks < nK2; ks++) {
            CP_WAIT0();
            __syncthreads();
            if (ks + 1 < nK2) {
                const uint32_t base = sb + ((ks + 1) & 1) * STAGE_B;
                const int k0 = (ks + 1) * KC;
                load_tile_async(base,          g_xf, arow, EMBED, k0, tid, 128);
                load_tile_async(base + TILE_B, g_wr, brow, EMBED, k0, tid, tmax);
                CP_COMMIT();
            }
            if (active)
                mma_stage(sb + (ks & 1) * STAGE_B, lane, warp_m, warp_n, acc);
        }

        // ---- store: acc/256 + br (cols < T), zeros to max_dim ----
#pragma unroll
        for (int i = 0; i < 4; i++) {
            const int rowA = warp_m * 64 + i * 16 + r0;
#pragma unroll
            for (int j = 0; j < 4; j++) {
                const int col = t0 + warp_n * 32 + j * 8 + c0;
                if (col >= max_dim) continue;
                float2 v0, v1;
                if (col < T) {
                    const float br0 = g_br[toff + col], br1 = g_br[toff + col + 1];
                    v0 = make_float2(acc[i][j][0] * INVWS + br0, acc[i][j][1] * INVWS + br1);
                    v1 = make_float2(acc[i][j][2] * INVWS + br0, acc[i][j][3] * INVWS + br1);
                } else {
                    v0 = make_float2(0.f, 0.f);
                    v1 = v0;
                }
                *reinterpret_cast<float2*>(outBase + (size_t)rowA * max_dim + col) = v0;
                *reinterpret_cast<float2*>(outBase + (size_t)(rowA + 8) * max_dim + col) = v1;
            }
        }
    }
}

// ----------------------------------------------------------------------------
extern "C" void kernel_launch(void* const* d_in, const int* in_sizes, int n_in,
                              void* d_out, int out_size)
{
    const float* x     = (const float*)d_in[0];
    const int*   psz   = (const int*)d_in[1];
    const float* W_in  = (const float*)d_in[2];
    const float* b_in  = (const float*)d_in[3];
    const float* W_sh  = (const float*)d_in[4];
    const float* b_sh  = (const float*)d_in[5];
    const float* W_res = (const float*)d_in[6];
    const float* b_res = (const float*)d_in[7];
    float* out = (float*)d_out;

    const int max_dim = out_size / (NSAMP * PTOK);
    const int ntiles = ((max_dim + 127) / 128) * NSAMP;

    cudaFuncSetAttribute(gemm1_kernel, cudaFuncAttributeMaxDynamicSharedMemorySize, SMEM_TOTAL);
    cudaFuncSetAttribute(head_kernel,  cudaFuncAttributeMaxDynamicSharedMemorySize, SMEM_TOTAL);

    // 1) vectorized prep (also resets head work-queue counter)
    {
        const long total = ((long)MROWS * EMBED + (long)INTER * EMBED
                          + (long)TTOT * INTER + (long)TTOT * EMBED + 2L * TTOT) / 8;
        prep_kernel<<<(unsigned)((total + 255) / 256), 256>>>(x, W_in, W_sh, b_sh, W_res, b_res);
    }
    // 2) xs = x @ W_in^T + b_in
    {
        dim3 g(INTER / 128, MROWS / 128);   // (32, 256)
        gemm1_kernel<<<g, 256, SMEM_TOTAL>>>(b_in);
    }
    // 3) persistent fused heads + zero padding (atomic tile queue)
    head_kernel<<<NPERS, 256, SMEM_TOTAL>>>(psz, out, max_dim, ntiles);
}